// round 12
// baseline (speedup 1.0000x reference)
#include <cuda_runtime.h>
#include <cuda_bf16.h>
#include <stdint.h>
#include <math.h>

#define BB 4
#define CC 64
#define HH 128
#define WW 128
#define OO 64
#define PIX 16384

// ---------------- device scratch ----------------
__device__ float g_offset[BB*18*PIX];
__device__ float g_mask[BB*9*PIX];
__device__ float g_xt[BB*PIX*CC];     // x NHWC
__device__ float g_gt[BB*PIX*CC];     // guide NHWC
// B weights prepacked in mma fragment order
__device__ uint4 g_oBh[4608];   // offmod: (chunk*8 + ks*2 + nhalf)*32 + lane
__device__ uint4 g_oBl[4608];
__device__ uint4 g_dBh[4608];   // deform: (kk*16 + ks*4 + nhalf*2 + p)*32 + lane
__device__ uint4 g_dBl[4608];

// ---------------- helpers ----------------
__device__ __forceinline__ uint32_t smem_u32(const void* p){
    uint32_t a;
    asm("{ .reg .u64 t; cvta.to.shared.u64 t, %1; cvt.u32.u64 %0, t; }" : "=r"(a) : "l"(p));
    return a;
}
__device__ __forceinline__ void ldsm4(uint32_t& r0, uint32_t& r1, uint32_t& r2, uint32_t& r3, uint32_t a){
    asm volatile("ldmatrix.sync.aligned.m8n8.x4.shared.b16 {%0,%1,%2,%3}, [%4];"
                 : "=r"(r0),"=r"(r1),"=r"(r2),"=r"(r3) : "r"(a));
}
__device__ __forceinline__ void mma16816(float* d, uint32_t a0, uint32_t a1, uint32_t a2, uint32_t a3,
                                         uint32_t b0, uint32_t b1){
    asm volatile("mma.sync.aligned.m16n8k16.row.col.f32.bf16.bf16.f32 "
                 "{%0,%1,%2,%3}, {%4,%5,%6,%7}, {%8,%9}, {%0,%1,%2,%3};"
                 : "+f"(d[0]),"+f"(d[1]),"+f"(d[2]),"+f"(d[3])
                 : "r"(a0),"r"(a1),"r"(a2),"r"(a3),"r"(b0),"r"(b1));
}
__device__ __forceinline__ void sts4(uint32_t a, uint32_t x, uint32_t y, uint32_t z, uint32_t w){
    asm volatile("st.shared.v4.u32 [%0], {%1,%2,%3,%4};" :: "r"(a),"r"(x),"r"(y),"r"(z),"r"(w) : "memory");
}
__device__ __forceinline__ void sts2(uint32_t a, uint32_t x, uint32_t y){
    asm volatile("st.shared.v2.u32 [%0], {%1,%2};" :: "r"(a),"r"(x),"r"(y) : "memory");
}
__device__ __forceinline__ void barp(int id){
    asm volatile("bar.sync %0, 64;" :: "r"(id) : "memory");
}
__device__ __forceinline__ uint32_t pk(float lo_e, float hi_e){
    uint32_t r;
    asm("cvt.rn.bf16x2.f32 %0, %1, %2;" : "=r"(r) : "f"(hi_e), "f"(lo_e));
    return r;
}
__device__ __forceinline__ float btrunc(float v){ return __bfloat162float(__float2bfloat16(v)); }

// ---------------------------------------------------------------------------
// Kernel 0: NCHW -> NHWC transpose (x and guide), vectorized both directions
// ---------------------------------------------------------------------------
__global__ void k_transpose(const float* __restrict__ x, const float* __restrict__ g){
    __shared__ float s[64*129];
    int h = blockIdx.x, b = blockIdx.y;
    const float* src = blockIdx.z ? g : x;
    float* dst       = blockIdx.z ? g_gt : g_xt;
    const float* xp = src + ((size_t)b*CC)*PIX + (size_t)h*WW;
    for (int i = threadIdx.x; i < 2048; i += 256) {
        int c = i >> 5, x4 = (i & 31) * 4;
        float4 v = *(const float4*)(xp + (size_t)c*PIX + x4);
        s[c*129 + x4+0]=v.x; s[c*129 + x4+1]=v.y; s[c*129 + x4+2]=v.z; s[c*129 + x4+3]=v.w;
    }
    __syncthreads();
    float* op = dst + ((size_t)(b*HH + h)*WW)*CC;
    for (int i = threadIdx.x; i < 2048; i += 256) {
        int xx = i >> 4, c4 = (i & 15) * 4;
        float4 v;
        v.x = s[(c4+0)*129 + xx];
        v.y = s[(c4+1)*129 + xx];
        v.z = s[(c4+2)*129 + xx];
        v.w = s[(c4+3)*129 + xx];
        *(float4*)(op + (size_t)xx*CC + c4) = v;
    }
}

// ---------------------------------------------------------------------------
// Kernel 1: weight prep — fp32 -> bf16 hi/lo, packed in mma fragment order.
// ---------------------------------------------------------------------------
__global__ void k_prepw(const float* __restrict__ w_off, const float* __restrict__ w_mod,
                        const float* __restrict__ w_reg){
    int i = blockIdx.x*256 + threadIdx.x;
    if (i >= 18432) return;
    int q = i & 3, L = (i >> 2) & 31;
    { // offmod: i = ((chunk*8 + ks*2 + nhalf)*32 + L)*4 + q
        int nhalf = (i >> 7) & 1, ks = (i >> 8) & 3, chunk = i >> 10;
        int kk = chunk >> 1, half = chunk & 1;
        int oc = nhalf*16 + ((q >> 1) & 1)*8 + (L >> 2);
        int ch = ks*16 + (q & 1)*8 + (L & 3)*2;
        int c0 = half*64 + ch;
        float w0 = 0.f, w1 = 0.f;
        if (oc < 18)      { w0 = w_off[(oc*128 + c0)*9 + kk];       w1 = w_off[(oc*128 + c0 + 1)*9 + kk]; }
        else if (oc < 27) { w0 = w_mod[((oc-18)*128 + c0)*9 + kk];  w1 = w_mod[((oc-18)*128 + c0 + 1)*9 + kk]; }
        float h0 = btrunc(w0), h1 = btrunc(w1);
        ((uint32_t*)g_oBh)[i] = pk(h0, h1);
        ((uint32_t*)g_oBl)[i] = pk(w0 - h0, w1 - h1);
    }
    { // deform: i = ((kk*16 + ks*4 + nhalf*2 + p)*32 + L)*4 + q
        int p = (i >> 7) & 1, nhalf = (i >> 8) & 1, ks = (i >> 9) & 3, kk = i >> 11;
        int oc = nhalf*32 + p*16 + ((q >> 1) & 1)*8 + (L >> 2);
        int ch = ks*16 + (q & 1)*8 + (L & 3)*2;
        float w0 = w_reg[(oc*64 + ch)*9 + kk], w1 = w_reg[(oc*64 + ch + 1)*9 + kk];
        float h0 = btrunc(w0), h1 = btrunc(w1);
        ((uint32_t*)g_dBh)[i] = pk(h0, h1);
        ((uint32_t*)g_dBl)[i] = pk(w0 - h0, w1 - h1);
    }
}

// ---------------------------------------------------------------------------
// Kernel 2: offset+modulator conv (M=128, N=32(27), K=1152).
// Single-buffered A (32KB) + direct-LDG fragment B -> 4 CTAs/SM. (R8, proven)
// ---------------------------------------------------------------------------
#define OM_AH 0
#define OM_AL 16384
#define OM_SMEM (32768 + 128)

__global__ __launch_bounds__(256,4) void k_offmod(const float* __restrict__ b_off,
                                                  const float* __restrict__ b_mod)
{
    extern __shared__ char smem_raw[];
    uint32_t sbr = smem_u32(smem_raw);
    uint32_t sb  = (sbr + 127) & ~127u;

    int t = threadIdx.x, wid = t >> 5, lid = t & 31;
    int mwid = wid & 3, nhalf = wid >> 2;
    int h = blockIdx.x, b = blockIdx.y;

    uint32_t aRowSel = (lid & 7) + ((lid >> 3) & 1) * 8;
    uint32_t aColSel = ((lid >> 4) & 1) * 16;
    uint32_t swz = (lid & 7) * 16;

    float acc[16];
#pragma unroll
    for (int i = 0; i < 16; i++) acc[i] = 0.f;

    for (int chunk = 0; chunk < 18; chunk++) {
        int kk = chunk >> 1, half = chunk & 1;
        int dy = kk/3 - 1, dx = kk%3 - 1;
        if (chunk) __syncthreads();
        { // stage A: [128 px][64 ch] of x/guide (NHWC) at (h+dy, px+dx)
            int hy = h + dy;
            bool rowok = (hy >= 0) && (hy < HH);
            const float* rowp = (half ? g_gt : g_xt) + (((size_t)b*HH + (rowok?hy:0))*WW)*CC;
#pragma unroll
            for (int jj = 0; jj < 4; jj++) {
                int i = jj*256 + t;
                int px = i >> 3, c8 = i & 7;
                int gx = px + dx;
                float v0=0,v1=0,v2=0,v3=0,v4=0,v5=0,v6=0,v7=0;
                if (rowok && gx >= 0 && gx < WW) {
                    const float4* p = (const float4*)(rowp + (size_t)gx*CC + c8*8);
                    float4 a = p[0], c = p[1];
                    v0=a.x; v1=a.y; v2=a.z; v3=a.w; v4=c.x; v5=c.y; v6=c.z; v7=c.w;
                }
                float w0=btrunc(v0),w1=btrunc(v1),w2=btrunc(v2),w3=btrunc(v3);
                float w4=btrunc(v4),w5=btrunc(v5),w6=btrunc(v6),w7=btrunc(v7);
                uint32_t off = px*128 + ((c8 ^ (px & 7)) * 16);
                sts4(sb + OM_AH + off, pk(v0,v1), pk(v2,v3), pk(v4,v5), pk(v6,v7));
                sts4(sb + OM_AL + off, pk(v0-w0,v1-w1), pk(v2-w2,v3-w3),
                                       pk(v4-w4,v5-w5), pk(v6-w6,v7-w7));
            }
        }
        __syncthreads();

#pragma unroll
        for (int ks = 0; ks < 4; ks++) {
            uint4 BH = g_oBh[(chunk*8 + ks*2 + nhalf)*32 + lid];
            uint4 BL = g_oBl[(chunk*8 + ks*2 + nhalf)*32 + lid];
            uint32_t ah[8], al[8];
#pragma unroll
            for (int m = 0; m < 2; m++) {
                uint32_t R = mwid*32 + m*16 + aRowSel;
                uint32_t aa = sb + OM_AH + R*128 + ((ks*32 + aColSel) ^ swz);
                ldsm4(ah[m*4+0], ah[m*4+1], ah[m*4+2], ah[m*4+3], aa);
                ldsm4(al[m*4+0], al[m*4+1], al[m*4+2], al[m*4+3], aa + 16384);
            }
#pragma unroll
            for (int m = 0; m < 2; m++) {
                float* d0 = acc + (m*2+0)*4;
                float* d1 = acc + (m*2+1)*4;
                mma16816(d0, ah[m*4+0],ah[m*4+1],ah[m*4+2],ah[m*4+3], BH.x, BH.y);
                mma16816(d0, al[m*4+0],al[m*4+1],al[m*4+2],al[m*4+3], BH.x, BH.y);
                mma16816(d0, ah[m*4+0],ah[m*4+1],ah[m*4+2],ah[m*4+3], BL.x, BL.y);
                mma16816(d1, ah[m*4+0],ah[m*4+1],ah[m*4+2],ah[m*4+3], BH.z, BH.w);
                mma16816(d1, al[m*4+0],al[m*4+1],al[m*4+2],al[m*4+3], BH.z, BH.w);
                mma16816(d1, ah[m*4+0],ah[m*4+1],ah[m*4+2],ah[m*4+3], BL.z, BL.w);
            }
        }
    }

    // epilogue
    int g = lid >> 2, tig = lid & 3;
    int pixbase = h*WW;
#pragma unroll
    for (int m = 0; m < 2; m++)
#pragma unroll
    for (int n = 0; n < 2; n++)
#pragma unroll
    for (int r = 0; r < 4; r++) {
        int px = mwid*32 + m*16 + g + (r>>1)*8;
        int oc = nhalf*16 + n*8 + 2*tig + (r&1);
        float v = acc[(m*2+n)*4 + r];
        int pix = pixbase + px;
        if (oc < 18) {
            g_offset[(size_t)(b*18 + oc)*PIX + pix] = v + b_off[oc];
        } else if (oc < 27) {
            float z = v + b_mod[oc-18];
            g_mask[(size_t)(b*9 + oc-18)*PIX + pix] = 2.f / (1.f + expf(-z));
        }
    }
}

// ---------------------------------------------------------------------------
// Kernel 3: deformable conv (M=128, N=64, K=576), PAIR-SPECIALIZED.
// 4 warp-pairs per CTA, each owning a private double-buffered 32-row A tile.
// Sync: 1 named barrier (64 threads) per kk per pair — no block barriers.
// smem: params (4KB: [wid][16px][8]) | A: [pair][buf][hi 4KB | lo 4KB] = 64KB
// ---------------------------------------------------------------------------
#define DF_PR 0
#define DF_A  4096
#define DF_SMEM (4096 + 65536 + 128)

__global__ __launch_bounds__(256,3) void k_deform(float* __restrict__ out)
{
    extern __shared__ char smem_raw[];
    uint32_t sbr = smem_u32(smem_raw);
    uint32_t sb  = (sbr + 127) & ~127u;
    char* sm0 = smem_raw + (sb - sbr);
    int*   spi = (int*)(sm0 + DF_PR);
    float* spf = (float*)(sm0 + DF_PR);

    int t = threadIdx.x, wid = t >> 5, lid = t & 31;
    int mwid = wid & 3, nhalf = wid >> 2;
    int h = blockIdx.x, b = blockIdx.y;

    uint32_t aRowSel = (lid & 7) + ((lid >> 3) & 1) * 8;
    uint32_t aColSel = ((lid >> 4) & 1) * 16;
    uint32_t swz = (lid & 7) * 16;

    const float4* xb4 = (const float4*)(g_xt + (size_t)b*PIX*CC);
    // pair A buffer bases (hi; lo = +4096)
    uint32_t pairA0 = sb + DF_A + (uint32_t)(mwid*2    )*8192;
    uint32_t pairA1 = sb + DF_A + (uint32_t)(mwid*2 + 1)*8192;
    int prbase = wid*128;   // int index into params region

    float acc[32];
#pragma unroll
    for (int i = 0; i < 32; i++) acc[i] = 0.f;

    // params for this warp's 16 px, chunk kk_  (lanes < 16)
#define DFP(kk_) do {                                                            \
    if (lid < 16) {                                                              \
        int px_ = mwid*32 + nhalf*16 + lid;                                      \
        int pix_ = h*WW + px_;                                                   \
        float oy_ = g_offset[((size_t)(b*18 + 2*(kk_)  ))*PIX + pix_];           \
        float ox_ = g_offset[((size_t)(b*18 + 2*(kk_)+1))*PIX + pix_];           \
        float m_  = g_mask  [((size_t)(b*9  + (kk_)    ))*PIX + pix_];           \
        int ky_ = (kk_)/3, kx_ = (kk_) - ky_*3;                                  \
        float py_  = oy_ + (float)(ky_ + h - 1);                                 \
        float pxf_ = ox_ + (float)(kx_ + px_ - 1);                               \
        float y0f_ = floorf(py_), x0f_ = floorf(pxf_);                           \
        int y0_ = (int)y0f_, x0_ = (int)x0f_;                                    \
        int y1_ = y0_ + 1,   x1_ = x0_ + 1;                                      \
        float wy1_ = py_ - y0f_,  wx1_ = pxf_ - x0f_;                            \
        float wy0_ = 1.f - wy1_, wx0_ = 1.f - wx1_;                              \
        bool vy0_ = (y0_>=0 && y0_<HH), vy1_ = (y1_>=0 && y1_<HH);               \
        bool vx0_ = (x0_>=0 && x0_<WW), vx1_ = (x1_>=0 && x1_<WW);               \
        int y0c_ = min(max(y0_,0),HH-1), y1c_ = min(max(y1_,0),HH-1);            \
        int x0c_ = min(max(x0_,0),WW-1), x1c_ = min(max(x1_,0),WW-1);            \
        int base_ = prbase + lid*8;                                              \
        spi[base_+0] = (y0c_*WW + x0c_)*16;                                      \
        spi[base_+1] = (y0c_*WW + x1c_)*16;                                      \
        spi[base_+2] = (y1c_*WW + x0c_)*16;                                      \
        spi[base_+3] = (y1c_*WW + x1c_)*16;                                      \
        spf[base_+4] = (vy0_&&vx0_) ? wy0_*wx0_*m_ : 0.f;                        \
        spf[base_+5] = (vy0_&&vx1_) ? wy0_*wx1_*m_ : 0.f;                        \
        spf[base_+6] = (vy1_&&vx0_) ? wy1_*wx0_*m_ : 0.f;                        \
        spf[base_+7] = (vy1_&&vx1_) ? wy1_*wx1_*m_ : 0.f;                        \
    } } while(0)

    // gather this warp's 16 px (local rows nhalf*16..+16) into pair buf `dstH`
#define DFG(dstH_) do {                                                          \
    _Pragma("unroll")                                                            \
    for (int it_ = 0; it_ < 8; it_++) {                                          \
        int j_ = it_*32 + lid;                                                   \
        int pxl_ = j_ >> 4, l16_ = j_ & 15;                                      \
        int r_ = nhalf*16 + pxl_;                                                \
        int base_ = prbase + pxl_*8;                                             \
        int i00 = spi[base_+0], i01 = spi[base_+1], i10 = spi[base_+2], i11 = spi[base_+3]; \
        float g00 = spf[base_+4], g01 = spf[base_+5], g10 = spf[base_+6], g11 = spf[base_+7]; \
        float4 a_ = xb4[i00 + l16_];                                             \
        float4 c_ = xb4[i01 + l16_];                                             \
        float4 d_ = xb4[i10 + l16_];                                             \
        float4 e_ = xb4[i11 + l16_];                                             \
        float v0 = g00*a_.x + g01*c_.x + g10*d_.x + g11*e_.x;                    \
        float v1 = g00*a_.y + g01*c_.y + g10*d_.y + g11*e_.y;                    \
        float v2 = g00*a_.z + g01*c_.z + g10*d_.z + g11*e_.z;                    \
        float v3 = g00*a_.w + g01*c_.w + g10*d_.w + g11*e_.w;                    \
        float w0=btrunc(v0), w1=btrunc(v1), w2=btrunc(v2), w3=btrunc(v3);        \
        uint32_t off_ = r_*128 + ((l16_*8) ^ ((r_ & 7)*16));                     \
        sts2((dstH_) + off_,        pk(v0,v1),       pk(v2,v3));                 \
        sts2((dstH_) + off_ + 4096, pk(v0-w0,v1-w1), pk(v2-w2,v3-w3));           \
    } } while(0)

    // prologue: fill buf0 for kk=0
    DFP(0);
    __syncwarp();
    DFG(pairA0);
    barp(mwid + 1);

    for (int kk = 0; kk < 9; kk++) {
        int s = kk & 1;
        if (kk < 8) {
            DFP(kk + 1);
            __syncwarp();
            DFG(s ? pairA0 : pairA1);
        }
        uint32_t aH = s ? pairA1 : pairA0;
#pragma unroll
        for (int ks = 0; ks < 4; ks++) {
            int bi = (kk*16 + ks*4 + nhalf*2)*32 + lid;
            uint4 BH0 = g_dBh[bi], BH1 = g_dBh[bi + 32];
            uint4 BL0 = g_dBl[bi], BL1 = g_dBl[bi + 32];
            uint32_t ah[8], al[8];
#pragma unroll
            for (int m = 0; m < 2; m++) {
                uint32_t R = m*16 + aRowSel;
                uint32_t aa = aH + R*128 + ((ks*32 + aColSel) ^ swz);
                ldsm4(ah[m*4+0], ah[m*4+1], ah[m*4+2], ah[m*4+3], aa);
                ldsm4(al[m*4+0], al[m*4+1], al[m*4+2], al[m*4+3], aa + 4096);
            }
#pragma unroll
            for (int m = 0; m < 2; m++) {
                float* d0 = acc + (m*4+0)*4;
                float* d1 = acc + (m*4+1)*4;
                float* d2 = acc + (m*4+2)*4;
                float* d3 = acc + (m*4+3)*4;
                mma16816(d0, ah[m*4+0],ah[m*4+1],ah[m*4+2],ah[m*4+3], BH0.x, BH0.y);
                mma16816(d0, al[m*4+0],al[m*4+1],al[m*4+2],al[m*4+3], BH0.x, BH0.y);
                mma16816(d0, ah[m*4+0],ah[m*4+1],ah[m*4+2],ah[m*4+3], BL0.x, BL0.y);
                mma16816(d1, ah[m*4+0],ah[m*4+1],ah[m*4+2],ah[m*4+3], BH0.z, BH0.w);
                mma16816(d1, al[m*4+0],al[m*4+1],al[m*4+2],al[m*4+3], BH0.z, BH0.w);
                mma16816(d1, ah[m*4+0],ah[m*4+1],ah[m*4+2],ah[m*4+3], BL0.z, BL0.w);
                mma16816(d2, ah[m*4+0],ah[m*4+1],ah[m*4+2],ah[m*4+3], BH1.x, BH1.y);
                mma16816(d2, al[m*4+0],al[m*4+1],al[m*4+2],al[m*4+3], BH1.x, BH1.y);
                mma16816(d2, ah[m*4+0],ah[m*4+1],ah[m*4+2],ah[m*4+3], BL1.x, BL1.y);
                mma16816(d3, ah[m*4+0],ah[m*4+1],ah[m*4+2],ah[m*4+3], BH1.z, BH1.w);
                mma16816(d3, al[m*4+0],al[m*4+1],al[m*4+2],al[m*4+3], BH1.z, BH1.w);
                mma16816(d3, ah[m*4+0],ah[m*4+1],ah[m*4+2],ah[m*4+3], BL1.z, BL1.w);
            }
        }
        barp(mwid + 1);
    }

    // epilogue
    int g = lid >> 2, tig = lid & 3;
    size_t ob = (size_t)b*64*PIX + (size_t)h*WW;
#pragma unroll
    for (int n = 0; n < 4; n++)
#pragma unroll
    for (int m = 0; m < 2; m++)
#pragma unroll
    for (int r = 0; r < 4; r++) {
        int px = mwid*32 + m*16 + g + (r>>1)*8;
        int oc = nhalf*32 + n*8 + 2*tig + (r&1);
        out[ob + (size_t)oc*PIX + px] = acc[(m*4+n)*4 + r];
    }
}

// ---------------------------------------------------------------------------
extern "C" void kernel_launch(void* const* d_in, const int* in_sizes, int n_in,
                              void* d_out, int out_size)
{
    const float* x     = (const float*)d_in[0];
    const float* guide = (const float*)d_in[1];
    const float* w_off = (const float*)d_in[2];
    const float* b_off = (const float*)d_in[3];
    const float* w_mod = (const float*)d_in[4];
    const float* b_mod = (const float*)d_in[5];
    const float* w_reg = (const float*)d_in[6];
    float* out = (float*)d_out;

    cudaFuncSetAttribute(k_offmod, cudaFuncAttributeMaxDynamicSharedMemorySize, OM_SMEM);
    cudaFuncSetAttribute(k_deform, cudaFuncAttributeMaxDynamicSharedMemorySize, DF_SMEM);

    k_transpose<<<dim3(HH, BB, 2), 256>>>(x, guide);
    k_prepw    <<<72, 256>>>(w_off, w_mod, w_reg);
    k_offmod   <<<dim3(HH, BB), 256, OM_SMEM>>>(b_off, b_mod);
    k_deform   <<<dim3(HH, BB), 256, DF_SMEM>>>(out);
}

// round 13
// speedup vs baseline: 1.2097x; 1.2097x over previous
#include <cuda_runtime.h>
#include <cuda_fp16.h>
#include <stdint.h>
#include <math.h>

#define BB 4
#define CC 64
#define HH 128
#define WW 128
#define OO 64
#define PIX 16384

// ---------------- device scratch ----------------
__device__ float g_offset[BB*18*PIX];
__device__ float g_mask[BB*9*PIX];
__device__ float g_xt[BB*PIX*CC];     // x NHWC
__device__ float g_gt[BB*PIX*CC];     // guide NHWC
// B weights (fp16 hi/lo) prepacked in mma fragment order
__device__ uint4 g_oBh[4608];   // offmod: (chunk*8 + ks*2 + nhalf)*32 + lane
__device__ uint4 g_oBl[4608];
__device__ uint4 g_dBh[4608];   // deform: (kk*16 + ks*4 + nhalf*2 + p)*32 + lane
__device__ uint4 g_dBl[4608];

// ---------------- helpers ----------------
__device__ __forceinline__ uint32_t smem_u32(const void* p){
    uint32_t a;
    asm("{ .reg .u64 t; cvta.to.shared.u64 t, %1; cvt.u32.u64 %0, t; }" : "=r"(a) : "l"(p));
    return a;
}
__device__ __forceinline__ void ldsm4(uint32_t& r0, uint32_t& r1, uint32_t& r2, uint32_t& r3, uint32_t a){
    asm volatile("ldmatrix.sync.aligned.m8n8.x4.shared.b16 {%0,%1,%2,%3}, [%4];"
                 : "=r"(r0),"=r"(r1),"=r"(r2),"=r"(r3) : "r"(a));
}
__device__ __forceinline__ void mma16816(float* d, uint32_t a0, uint32_t a1, uint32_t a2, uint32_t a3,
                                         uint32_t b0, uint32_t b1){
    asm volatile("mma.sync.aligned.m16n8k16.row.col.f32.f16.f16.f32 "
                 "{%0,%1,%2,%3}, {%4,%5,%6,%7}, {%8,%9}, {%0,%1,%2,%3};"
                 : "+f"(d[0]),"+f"(d[1]),"+f"(d[2]),"+f"(d[3])
                 : "r"(a0),"r"(a1),"r"(a2),"r"(a3),"r"(b0),"r"(b1));
}
__device__ __forceinline__ void sts4(uint32_t a, uint32_t x, uint32_t y, uint32_t z, uint32_t w){
    asm volatile("st.shared.v4.u32 [%0], {%1,%2,%3,%4};" :: "r"(a),"r"(x),"r"(y),"r"(z),"r"(w) : "memory");
}
__device__ __forceinline__ void sts2(uint32_t a, uint32_t x, uint32_t y){
    asm volatile("st.shared.v2.u32 [%0], {%1,%2};" :: "r"(a),"r"(x),"r"(y) : "memory");
}
__device__ __forceinline__ uint32_t pk16(float lo_e, float hi_e){
    uint32_t r;
    asm("cvt.rn.f16x2.f32 %0, %1, %2;" : "=r"(r) : "f"(hi_e), "f"(lo_e));
    return r;
}

// ---------------------------------------------------------------------------
// Kernel 0: NCHW -> NHWC transpose (x and guide), vectorized both directions
// ---------------------------------------------------------------------------
__global__ void k_transpose(const float* __restrict__ x, const float* __restrict__ g){
    __shared__ float s[64*129];
    int h = blockIdx.x, b = blockIdx.y;
    const float* src = blockIdx.z ? g : x;
    float* dst       = blockIdx.z ? g_gt : g_xt;
    const float* xp = src + ((size_t)b*CC)*PIX + (size_t)h*WW;
    for (int i = threadIdx.x; i < 2048; i += 256) {
        int c = i >> 5, x4 = (i & 31) * 4;
        float4 v = *(const float4*)(xp + (size_t)c*PIX + x4);
        s[c*129 + x4+0]=v.x; s[c*129 + x4+1]=v.y; s[c*129 + x4+2]=v.z; s[c*129 + x4+3]=v.w;
    }
    __syncthreads();
    float* op = dst + ((size_t)(b*HH + h)*WW)*CC;
    for (int i = threadIdx.x; i < 2048; i += 256) {
        int xx = i >> 4, c4 = (i & 15) * 4;
        float4 v;
        v.x = s[(c4+0)*129 + xx];
        v.y = s[(c4+1)*129 + xx];
        v.z = s[(c4+2)*129 + xx];
        v.w = s[(c4+3)*129 + xx];
        *(float4*)(op + (size_t)xx*CC + c4) = v;
    }
}

// ---------------------------------------------------------------------------
// Kernel 1: weight prep — fp32 -> fp16 hi/lo, packed in mma fragment order.
//   reg j (0..3): oc = base + ((j>>1)&1)*8 + (L>>2), ch = ks*16 + (j&1)*8 + (L&3)*2
// ---------------------------------------------------------------------------
__global__ void k_prepw(const float* __restrict__ w_off, const float* __restrict__ w_mod,
                        const float* __restrict__ w_reg){
    int i = blockIdx.x*256 + threadIdx.x;
    if (i >= 18432) return;
    int q = i & 3, L = (i >> 2) & 31;
    { // offmod: i = ((chunk*8 + ks*2 + nhalf)*32 + L)*4 + q
        int nhalf = (i >> 7) & 1, ks = (i >> 8) & 3, chunk = i >> 10;
        int kk = chunk >> 1, half = chunk & 1;
        int oc = nhalf*16 + ((q >> 1) & 1)*8 + (L >> 2);
        int ch = ks*16 + (q & 1)*8 + (L & 3)*2;
        int c0 = half*64 + ch;
        float w0 = 0.f, w1 = 0.f;
        if (oc < 18)      { w0 = w_off[(oc*128 + c0)*9 + kk];       w1 = w_off[(oc*128 + c0 + 1)*9 + kk]; }
        else if (oc < 27) { w0 = w_mod[((oc-18)*128 + c0)*9 + kk];  w1 = w_mod[((oc-18)*128 + c0 + 1)*9 + kk]; }
        float h0 = __half2float(__float2half_rn(w0));
        float h1 = __half2float(__float2half_rn(w1));
        ((uint32_t*)g_oBh)[i] = pk16(h0, h1);
        ((uint32_t*)g_oBl)[i] = pk16(w0 - h0, w1 - h1);
    }
    { // deform: i = ((kk*16 + ks*4 + nhalf*2 + p)*32 + L)*4 + q
        int p = (i >> 7) & 1, nhalf = (i >> 8) & 1, ks = (i >> 9) & 3, kk = i >> 11;
        int oc = nhalf*32 + p*16 + ((q >> 1) & 1)*8 + (L >> 2);
        int ch = ks*16 + (q & 1)*8 + (L & 3)*2;
        float w0 = w_reg[(oc*64 + ch)*9 + kk], w1 = w_reg[(oc*64 + ch + 1)*9 + kk];
        float h0 = __half2float(__float2half_rn(w0));
        float h1 = __half2float(__float2half_rn(w1));
        ((uint32_t*)g_dBh)[i] = pk16(h0, h1);
        ((uint32_t*)g_dBl)[i] = pk16(w0 - h0, w1 - h1);
    }
}

// ---------------------------------------------------------------------------
// Kernel 2: offset+modulator conv (M=128, N=32(27), K=1152).
// A single fp16 (16KB) + direct-LDG fragment B (hi/lo) -> 4 CTAs/SM.
// D = A*Bh + A*Bl  (2-term fp16; A unsplit)
// ---------------------------------------------------------------------------
#define OM_AH 0
#define OM_SMEM (16384 + 128)

__global__ __launch_bounds__(256,4) void k_offmod(const float* __restrict__ b_off,
                                                  const float* __restrict__ b_mod)
{
    extern __shared__ char smem_raw[];
    uint32_t sbr = smem_u32(smem_raw);
    uint32_t sb  = (sbr + 127) & ~127u;

    int t = threadIdx.x, wid = t >> 5, lid = t & 31;
    int mwid = wid & 3, nhalf = wid >> 2;
    int h = blockIdx.x, b = blockIdx.y;

    uint32_t aRowSel = (lid & 7) + ((lid >> 3) & 1) * 8;
    uint32_t aColSel = ((lid >> 4) & 1) * 16;
    uint32_t swz = (lid & 7) * 16;

    float acc[16];
#pragma unroll
    for (int i = 0; i < 16; i++) acc[i] = 0.f;

    for (int chunk = 0; chunk < 18; chunk++) {
        int kk = chunk >> 1, half = chunk & 1;
        int dy = kk/3 - 1, dx = kk%3 - 1;
        if (chunk) __syncthreads();
        { // stage A: [128 px][64 ch] of x/guide (NHWC) at (h+dy, px+dx), fp16
            int hy = h + dy;
            bool rowok = (hy >= 0) && (hy < HH);
            const float* rowp = (half ? g_gt : g_xt) + (((size_t)b*HH + (rowok?hy:0))*WW)*CC;
#pragma unroll
            for (int jj = 0; jj < 4; jj++) {
                int i = jj*256 + t;
                int px = i >> 3, c8 = i & 7;
                int gx = px + dx;
                float v0=0,v1=0,v2=0,v3=0,v4=0,v5=0,v6=0,v7=0;
                if (rowok && gx >= 0 && gx < WW) {
                    const float4* p = (const float4*)(rowp + (size_t)gx*CC + c8*8);
                    float4 a = p[0], c = p[1];
                    v0=a.x; v1=a.y; v2=a.z; v3=a.w; v4=c.x; v5=c.y; v6=c.z; v7=c.w;
                }
                uint32_t off = px*128 + ((c8 ^ (px & 7)) * 16);
                sts4(sb + OM_AH + off, pk16(v0,v1), pk16(v2,v3), pk16(v4,v5), pk16(v6,v7));
            }
        }
        __syncthreads();

#pragma unroll
        for (int ks = 0; ks < 4; ks++) {
            uint4 BH = g_oBh[(chunk*8 + ks*2 + nhalf)*32 + lid];
            uint4 BL = g_oBl[(chunk*8 + ks*2 + nhalf)*32 + lid];
            uint32_t ah[8];
#pragma unroll
            for (int m = 0; m < 2; m++) {
                uint32_t R = mwid*32 + m*16 + aRowSel;
                uint32_t aa = sb + OM_AH + R*128 + ((ks*32 + aColSel) ^ swz);
                ldsm4(ah[m*4+0], ah[m*4+1], ah[m*4+2], ah[m*4+3], aa);
            }
#pragma unroll
            for (int m = 0; m < 2; m++) {
                float* d0 = acc + (m*2+0)*4;
                float* d1 = acc + (m*2+1)*4;
                mma16816(d0, ah[m*4+0],ah[m*4+1],ah[m*4+2],ah[m*4+3], BH.x, BH.y);
                mma16816(d0, ah[m*4+0],ah[m*4+1],ah[m*4+2],ah[m*4+3], BL.x, BL.y);
                mma16816(d1, ah[m*4+0],ah[m*4+1],ah[m*4+2],ah[m*4+3], BH.z, BH.w);
                mma16816(d1, ah[m*4+0],ah[m*4+1],ah[m*4+2],ah[m*4+3], BL.z, BL.w);
            }
        }
    }

    // epilogue
    int g = lid >> 2, tig = lid & 3;
    int pixbase = h*WW;
#pragma unroll
    for (int m = 0; m < 2; m++)
#pragma unroll
    for (int n = 0; n < 2; n++)
#pragma unroll
    for (int r = 0; r < 4; r++) {
        int px = mwid*32 + m*16 + g + (r>>1)*8;
        int oc = nhalf*16 + n*8 + 2*tig + (r&1);
        float v = acc[(m*2+n)*4 + r];
        int pix = pixbase + px;
        if (oc < 18) {
            g_offset[(size_t)(b*18 + oc)*PIX + pix] = v + b_off[oc];
        } else if (oc < 27) {
            float z = v + b_mod[oc-18];
            g_mask[(size_t)(b*9 + oc-18)*PIX + pix] = 2.f / (1.f + expf(-z));
        }
    }
}

// ---------------------------------------------------------------------------
// Kernel 3: deformable conv (M=128, N=64, K=576), pipelined (R11 structure).
// A single fp16, double-buffered (2x16KB); params double-buffered; B hi/lo LDG.
// D = A*Bh + A*Bl  (2-term fp16)
// ---------------------------------------------------------------------------
#define DF_PB  0
#define DF_A0  8192
#define DF_A1  24576
#define DF_SMEM (40960 + 128)

__global__ __launch_bounds__(256,3) void k_deform(float* __restrict__ out)
{
    extern __shared__ char smem_raw[];
    uint32_t sbr = smem_u32(smem_raw);
    uint32_t sb  = (sbr + 127) & ~127u;
    char* sm0 = smem_raw + (sb - sbr);
    int*   spi = (int*)(sm0 + DF_PB);
    float* spf = (float*)(sm0 + DF_PB);

    int t = threadIdx.x, wid = t >> 5, lid = t & 31;
    int mwid = wid & 3, nhalf = wid >> 2;
    int h = blockIdx.x, b = blockIdx.y;

    uint32_t aRowSel = (lid & 7) + ((lid >> 3) & 1) * 8;
    uint32_t aColSel = ((lid >> 4) & 1) * 16;
    uint32_t swz = (lid & 7) * 16;

    const float4* xb4 = (const float4*)(g_xt + (size_t)b*PIX*CC);

    float acc[32];
#pragma unroll
    for (int i = 0; i < 32; i++) acc[i] = 0.f;

#define DF_PARAMS(kk_, psel_) do {                                               \
    if (t < 128) {                                                               \
        int px_ = t;                                                             \
        int pix_ = h*WW + px_;                                                   \
        float oy_ = g_offset[((size_t)(b*18 + 2*(kk_)  ))*PIX + pix_];           \
        float ox_ = g_offset[((size_t)(b*18 + 2*(kk_)+1))*PIX + pix_];           \
        float m_  = g_mask  [((size_t)(b*9  + (kk_)    ))*PIX + pix_];           \
        int ky_ = (kk_)/3, kx_ = (kk_) - ky_*3;                                  \
        float py_  = oy_ + (float)(ky_ + h - 1);                                 \
        float pxf_ = ox_ + (float)(kx_ + px_ - 1);                               \
        float y0f_ = floorf(py_), x0f_ = floorf(pxf_);                           \
        int y0_ = (int)y0f_, x0_ = (int)x0f_;                                    \
        int y1_ = y0_ + 1,   x1_ = x0_ + 1;                                      \
        float wy1_ = py_ - y0f_,  wx1_ = pxf_ - x0f_;                            \
        float wy0_ = 1.f - wy1_, wx0_ = 1.f - wx1_;                              \
        bool vy0_ = (y0_>=0 && y0_<HH), vy1_ = (y1_>=0 && y1_<HH);               \
        bool vx0_ = (x0_>=0 && x0_<WW), vx1_ = (x1_>=0 && x1_<WW);               \
        int y0c_ = min(max(y0_,0),HH-1), y1c_ = min(max(y1_,0),HH-1);            \
        int x0c_ = min(max(x0_,0),WW-1), x1c_ = min(max(x1_,0),WW-1);            \
        int base_ = (psel_)*1024 + px_*8;                                        \
        spi[base_+0] = (y0c_*WW + x0c_)*16;                                      \
        spi[base_+1] = (y0c_*WW + x1c_)*16;                                      \
        spi[base_+2] = (y1c_*WW + x0c_)*16;                                      \
        spi[base_+3] = (y1c_*WW + x1c_)*16;                                      \
        spf[base_+4] = (vy0_&&vx0_) ? wy0_*wx0_*m_ : 0.f;                        \
        spf[base_+5] = (vy0_&&vx1_) ? wy0_*wx1_*m_ : 0.f;                        \
        spf[base_+6] = (vy1_&&vx0_) ? wy1_*wx0_*m_ : 0.f;                        \
        spf[base_+7] = (vy1_&&vx1_) ? wy1_*wx1_*m_ : 0.f;                        \
    } } while(0)

#define DF_GATHER(psel_, dH_) do {                                               \
    _Pragma("unroll")                                                            \
    for (int it_ = 0; it_ < 8; it_++) {                                          \
        int j_ = it_*256 + t;                                                    \
        int px_ = j_ >> 4, l16_ = j_ & 15;                                       \
        int base_ = (psel_)*1024 + px_*8;                                        \
        int i00 = spi[base_+0], i01 = spi[base_+1], i10 = spi[base_+2], i11 = spi[base_+3]; \
        float g00 = spf[base_+4], g01 = spf[base_+5], g10 = spf[base_+6], g11 = spf[base_+7]; \
        float4 a_ = xb4[i00 + l16_];                                             \
        float4 c_ = xb4[i01 + l16_];                                             \
        float4 d_ = xb4[i10 + l16_];                                             \
        float4 e_ = xb4[i11 + l16_];                                             \
        float v0 = g00*a_.x + g01*c_.x + g10*d_.x + g11*e_.x;                    \
        float v1 = g00*a_.y + g01*c_.y + g10*d_.y + g11*e_.y;                    \
        float v2 = g00*a_.z + g01*c_.z + g10*d_.z + g11*e_.z;                    \
        float v3 = g00*a_.w + g01*c_.w + g10*d_.w + g11*e_.w;                    \
        uint32_t off_ = px_*128 + ((l16_*8) ^ ((px_ & 7)*16));                   \
        sts2(sb + (dH_) + off_, pk16(v0,v1), pk16(v2,v3));                       \
    } } while(0)

    // prologue
    DF_PARAMS(0, 0);
    __syncthreads();
    DF_GATHER(0, DF_A0);
    DF_PARAMS(1, 1);
    __syncthreads();

    for (int kk = 0; kk < 9; kk++) {
        int cs = kk & 1, ns = cs ^ 1;
        if (kk < 8) {
            if (ns) DF_GATHER(1, DF_A1);
            else    DF_GATHER(0, DF_A0);
        }
        if (kk < 7) DF_PARAMS(kk+2, cs);

        uint32_t aH = sb + (cs ? DF_A1 : DF_A0);
#pragma unroll
        for (int ks = 0; ks < 4; ks++) {
            int bi = (kk*16 + ks*4 + nhalf*2)*32 + lid;
            uint4 BH0 = g_dBh[bi], BH1 = g_dBh[bi + 32];
            uint4 BL0 = g_dBl[bi], BL1 = g_dBl[bi + 32];
            uint32_t ah[8];
#pragma unroll
            for (int m = 0; m < 2; m++) {
                uint32_t R = mwid*32 + m*16 + aRowSel;
                uint32_t aa = aH + R*128 + ((ks*32 + aColSel) ^ swz);
                ldsm4(ah[m*4+0], ah[m*4+1], ah[m*4+2], ah[m*4+3], aa);
            }
#pragma unroll
            for (int m = 0; m < 2; m++) {
                float* d0 = acc + (m*4+0)*4;
                float* d1 = acc + (m*4+1)*4;
                float* d2 = acc + (m*4+2)*4;
                float* d3 = acc + (m*4+3)*4;
                mma16816(d0, ah[m*4+0],ah[m*4+1],ah[m*4+2],ah[m*4+3], BH0.x, BH0.y);
                mma16816(d0, ah[m*4+0],ah[m*4+1],ah[m*4+2],ah[m*4+3], BL0.x, BL0.y);
                mma16816(d1, ah[m*4+0],ah[m*4+1],ah[m*4+2],ah[m*4+3], BH0.z, BH0.w);
                mma16816(d1, ah[m*4+0],ah[m*4+1],ah[m*4+2],ah[m*4+3], BL0.z, BL0.w);
                mma16816(d2, ah[m*4+0],ah[m*4+1],ah[m*4+2],ah[m*4+3], BH1.x, BH1.y);
                mma16816(d2, ah[m*4+0],ah[m*4+1],ah[m*4+2],ah[m*4+3], BL1.x, BL1.y);
                mma16816(d3, ah[m*4+0],ah[m*4+1],ah[m*4+2],ah[m*4+3], BH1.z, BH1.w);
                mma16816(d3, ah[m*4+0],ah[m*4+1],ah[m*4+2],ah[m*4+3], BL1.z, BL1.w);
            }
        }
        __syncthreads();
    }

    // epilogue
    int g = lid >> 2, tig = lid & 3;
    size_t ob = (size_t)b*64*PIX + (size_t)h*WW;
#pragma unroll
    for (int n = 0; n < 4; n++)
#pragma unroll
    for (int m = 0; m < 2; m++)
#pragma unroll
    for (int r = 0; r < 4; r++) {
        int px = mwid*32 + m*16 + g + (r>>1)*8;
        int oc = nhalf*32 + n*8 + 2*tig + (r&1);
        out[ob + (size_t)oc*PIX + px] = acc[(m*4+n)*4 + r];
    }
}

// ---------------------------------------------------------------------------
extern "C" void kernel_launch(void* const* d_in, const int* in_sizes, int n_in,
                              void* d_out, int out_size)
{
    const float* x     = (const float*)d_in[0];
    const float* guide = (const float*)d_in[1];
    const float* w_off = (const float*)d_in[2];
    const float* b_off = (const float*)d_in[3];
    const float* w_mod = (const float*)d_in[4];
    const float* b_mod = (const float*)d_in[5];
    const float* w_reg = (const float*)d_in[6];
    float* out = (float*)d_out;

    cudaFuncSetAttribute(k_offmod, cudaFuncAttributeMaxDynamicSharedMemorySize, OM_SMEM);
    cudaFuncSetAttribute(k_deform, cudaFuncAttributeMaxDynamicSharedMemorySize, DF_SMEM);

    k_transpose<<<dim3(HH, BB, 2), 256>>>(x, guide);
    k_prepw    <<<72, 256>>>(w_off, w_mod, w_reg);
    k_offmod   <<<dim3(HH, BB), 256, OM_SMEM>>>(b_off, b_mod);
    k_deform   <<<dim3(HH, BB), 256, DF_SMEM>>>(out);
}

// round 14
// speedup vs baseline: 1.2508x; 1.0340x over previous
#include <cuda_runtime.h>
#include <cuda_fp16.h>
#include <stdint.h>
#include <math.h>

#define BB 4
#define CC 64
#define HH 128
#define WW 128
#define OO 64
#define PIX 16384

// ---------------- device scratch ----------------
__device__ float g_offset[BB*18*PIX];
__device__ float g_mask[BB*9*PIX];
__device__ float g_xt[BB*PIX*CC];     // x NHWC
__device__ float g_gt[BB*PIX*CC];     // guide NHWC
// B weights (fp16 hi/lo) prepacked in mma fragment order
__device__ uint4 g_oBh[4608];   // offmod: (chunk*8 + ks*2 + nhalf)*32 + lane
__device__ uint4 g_oBl[4608];
__device__ uint4 g_dBh[4608];   // deform: (kk*16 + ks*4 + nhalf*2 + p)*32 + lane
__device__ uint4 g_dBl[4608];

// ---------------- helpers ----------------
__device__ __forceinline__ uint32_t smem_u32(const void* p){
    uint32_t a;
    asm("{ .reg .u64 t; cvta.to.shared.u64 t, %1; cvt.u32.u64 %0, t; }" : "=r"(a) : "l"(p));
    return a;
}
__device__ __forceinline__ void ldsm4(uint32_t& r0, uint32_t& r1, uint32_t& r2, uint32_t& r3, uint32_t a){
    asm volatile("ldmatrix.sync.aligned.m8n8.x4.shared.b16 {%0,%1,%2,%3}, [%4];"
                 : "=r"(r0),"=r"(r1),"=r"(r2),"=r"(r3) : "r"(a));
}
__device__ __forceinline__ void mma16816(float* d, uint32_t a0, uint32_t a1, uint32_t a2, uint32_t a3,
                                         uint32_t b0, uint32_t b1){
    asm volatile("mma.sync.aligned.m16n8k16.row.col.f32.f16.f16.f32 "
                 "{%0,%1,%2,%3}, {%4,%5,%6,%7}, {%8,%9}, {%0,%1,%2,%3};"
                 : "+f"(d[0]),"+f"(d[1]),"+f"(d[2]),"+f"(d[3])
                 : "r"(a0),"r"(a1),"r"(a2),"r"(a3),"r"(b0),"r"(b1));
}
__device__ __forceinline__ void sts4(uint32_t a, uint32_t x, uint32_t y, uint32_t z, uint32_t w){
    asm volatile("st.shared.v4.u32 [%0], {%1,%2,%3,%4};" :: "r"(a),"r"(x),"r"(y),"r"(z),"r"(w) : "memory");
}
__device__ __forceinline__ void sts2(uint32_t a, uint32_t x, uint32_t y){
    asm volatile("st.shared.v2.u32 [%0], {%1,%2};" :: "r"(a),"r"(x),"r"(y) : "memory");
}
__device__ __forceinline__ uint32_t pk16(float lo_e, float hi_e){
    uint32_t r;
    asm("cvt.rn.f16x2.f32 %0, %1, %2;" : "=r"(r) : "f"(hi_e), "f"(lo_e));
    return r;
}

// ---------------------------------------------------------------------------
// Kernel 0: NCHW -> NHWC transpose (x and guide), vectorized both directions
// ---------------------------------------------------------------------------
__global__ void k_transpose(const float* __restrict__ x, const float* __restrict__ g){
    __shared__ float s[64*129];
    int h = blockIdx.x, b = blockIdx.y;
    const float* src = blockIdx.z ? g : x;
    float* dst       = blockIdx.z ? g_gt : g_xt;
    const float* xp = src + ((size_t)b*CC)*PIX + (size_t)h*WW;
    for (int i = threadIdx.x; i < 2048; i += 256) {
        int c = i >> 5, x4 = (i & 31) * 4;
        float4 v = *(const float4*)(xp + (size_t)c*PIX + x4);
        s[c*129 + x4+0]=v.x; s[c*129 + x4+1]=v.y; s[c*129 + x4+2]=v.z; s[c*129 + x4+3]=v.w;
    }
    __syncthreads();
    float* op = dst + ((size_t)(b*HH + h)*WW)*CC;
    for (int i = threadIdx.x; i < 2048; i += 256) {
        int xx = i >> 4, c4 = (i & 15) * 4;
        float4 v;
        v.x = s[(c4+0)*129 + xx];
        v.y = s[(c4+1)*129 + xx];
        v.z = s[(c4+2)*129 + xx];
        v.w = s[(c4+3)*129 + xx];
        *(float4*)(op + (size_t)xx*CC + c4) = v;
    }
}

// ---------------------------------------------------------------------------
// Kernel 1: weight prep — fp32 -> fp16 hi/lo, packed in mma fragment order.
// ---------------------------------------------------------------------------
__global__ void k_prepw(const float* __restrict__ w_off, const float* __restrict__ w_mod,
                        const float* __restrict__ w_reg){
    int i = blockIdx.x*256 + threadIdx.x;
    if (i >= 18432) return;
    int q = i & 3, L = (i >> 2) & 31;
    { // offmod
        int nhalf = (i >> 7) & 1, ks = (i >> 8) & 3, chunk = i >> 10;
        int kk = chunk >> 1, half = chunk & 1;
        int oc = nhalf*16 + ((q >> 1) & 1)*8 + (L >> 2);
        int ch = ks*16 + (q & 1)*8 + (L & 3)*2;
        int c0 = half*64 + ch;
        float w0 = 0.f, w1 = 0.f;
        if (oc < 18)      { w0 = w_off[(oc*128 + c0)*9 + kk];       w1 = w_off[(oc*128 + c0 + 1)*9 + kk]; }
        else if (oc < 27) { w0 = w_mod[((oc-18)*128 + c0)*9 + kk];  w1 = w_mod[((oc-18)*128 + c0 + 1)*9 + kk]; }
        float h0 = __half2float(__float2half_rn(w0));
        float h1 = __half2float(__float2half_rn(w1));
        ((uint32_t*)g_oBh)[i] = pk16(h0, h1);
        ((uint32_t*)g_oBl)[i] = pk16(w0 - h0, w1 - h1);
    }
    { // deform
        int p = (i >> 7) & 1, nhalf = (i >> 8) & 1, ks = (i >> 9) & 3, kk = i >> 11;
        int oc = nhalf*32 + p*16 + ((q >> 1) & 1)*8 + (L >> 2);
        int ch = ks*16 + (q & 1)*8 + (L & 3)*2;
        float w0 = w_reg[(oc*64 + ch)*9 + kk], w1 = w_reg[(oc*64 + ch + 1)*9 + kk];
        float h0 = __half2float(__float2half_rn(w0));
        float h1 = __half2float(__float2half_rn(w1));
        ((uint32_t*)g_dBh)[i] = pk16(h0, h1);
        ((uint32_t*)g_dBl)[i] = pk16(w0 - h0, w1 - h1);
    }
}

// ---------------------------------------------------------------------------
// Kernel 2: offset+modulator conv (M=128, N=32(27), K=1152).
// A single fp16 (16KB) + direct-LDG fragment B (hi/lo) -> 4 CTAs/SM.
// ---------------------------------------------------------------------------
#define OM_AH 0
#define OM_SMEM (16384 + 128)

__global__ __launch_bounds__(256,4) void k_offmod(const float* __restrict__ b_off,
                                                  const float* __restrict__ b_mod)
{
    extern __shared__ char smem_raw[];
    uint32_t sbr = smem_u32(smem_raw);
    uint32_t sb  = (sbr + 127) & ~127u;

    int t = threadIdx.x, wid = t >> 5, lid = t & 31;
    int mwid = wid & 3, nhalf = wid >> 2;
    int h = blockIdx.x, b = blockIdx.y;

    uint32_t aRowSel = (lid & 7) + ((lid >> 3) & 1) * 8;
    uint32_t aColSel = ((lid >> 4) & 1) * 16;
    uint32_t swz = (lid & 7) * 16;

    float acc[16];
#pragma unroll
    for (int i = 0; i < 16; i++) acc[i] = 0.f;

    for (int chunk = 0; chunk < 18; chunk++) {
        int kk = chunk >> 1, half = chunk & 1;
        int dy = kk/3 - 1, dx = kk%3 - 1;
        if (chunk) __syncthreads();
        { // stage A
            int hy = h + dy;
            bool rowok = (hy >= 0) && (hy < HH);
            const float* rowp = (half ? g_gt : g_xt) + (((size_t)b*HH + (rowok?hy:0))*WW)*CC;
#pragma unroll
            for (int jj = 0; jj < 4; jj++) {
                int i = jj*256 + t;
                int px = i >> 3, c8 = i & 7;
                int gx = px + dx;
                float v0=0,v1=0,v2=0,v3=0,v4=0,v5=0,v6=0,v7=0;
                if (rowok && gx >= 0 && gx < WW) {
                    const float4* p = (const float4*)(rowp + (size_t)gx*CC + c8*8);
                    float4 a = p[0], c = p[1];
                    v0=a.x; v1=a.y; v2=a.z; v3=a.w; v4=c.x; v5=c.y; v6=c.z; v7=c.w;
                }
                uint32_t off = px*128 + ((c8 ^ (px & 7)) * 16);
                sts4(sb + OM_AH + off, pk16(v0,v1), pk16(v2,v3), pk16(v4,v5), pk16(v6,v7));
            }
        }
        __syncthreads();

#pragma unroll
        for (int ks = 0; ks < 4; ks++) {
            uint4 BH = g_oBh[(chunk*8 + ks*2 + nhalf)*32 + lid];
            uint4 BL = g_oBl[(chunk*8 + ks*2 + nhalf)*32 + lid];
            uint32_t ah[8];
#pragma unroll
            for (int m = 0; m < 2; m++) {
                uint32_t R = mwid*32 + m*16 + aRowSel;
                uint32_t aa = sb + OM_AH + R*128 + ((ks*32 + aColSel) ^ swz);
                ldsm4(ah[m*4+0], ah[m*4+1], ah[m*4+2], ah[m*4+3], aa);
            }
#pragma unroll
            for (int m = 0; m < 2; m++) {
                float* d0 = acc + (m*2+0)*4;
                float* d1 = acc + (m*2+1)*4;
                mma16816(d0, ah[m*4+0],ah[m*4+1],ah[m*4+2],ah[m*4+3], BH.x, BH.y);
                mma16816(d0, ah[m*4+0],ah[m*4+1],ah[m*4+2],ah[m*4+3], BL.x, BL.y);
                mma16816(d1, ah[m*4+0],ah[m*4+1],ah[m*4+2],ah[m*4+3], BH.z, BH.w);
                mma16816(d1, ah[m*4+0],ah[m*4+1],ah[m*4+2],ah[m*4+3], BL.z, BL.w);
            }
        }
    }

    // epilogue
    int g = lid >> 2, tig = lid & 3;
    int pixbase = h*WW;
#pragma unroll
    for (int m = 0; m < 2; m++)
#pragma unroll
    for (int n = 0; n < 2; n++)
#pragma unroll
    for (int r = 0; r < 4; r++) {
        int px = mwid*32 + m*16 + g + (r>>1)*8;
        int oc = nhalf*16 + n*8 + 2*tig + (r&1);
        float v = acc[(m*2+n)*4 + r];
        int pix = pixbase + px;
        if (oc < 18) {
            g_offset[(size_t)(b*18 + oc)*PIX + pix] = v + b_off[oc];
        } else if (oc < 27) {
            float z = v + b_mod[oc-18];
            g_mask[(size_t)(b*9 + oc-18)*PIX + pix] = 2.f / (1.f + expf(-z));
        }
    }
}

// ---------------------------------------------------------------------------
// Kernel 3: deformable conv (M=128, N=64, K=576), pipelined fp16 2-term.
// 4 CTAs/SM (single wave for grid 512). B consumed in two halves to fit 64 regs.
// ---------------------------------------------------------------------------
#define DF_PB  0
#define DF_A0  8192
#define DF_A1  24576
#define DF_SMEM (40960 + 128)

__global__ __launch_bounds__(256,4) void k_deform(float* __restrict__ out)
{
    extern __shared__ char smem_raw[];
    uint32_t sbr = smem_u32(smem_raw);
    uint32_t sb  = (sbr + 127) & ~127u;
    char* sm0 = smem_raw + (sb - sbr);
    int*   spi = (int*)(sm0 + DF_PB);
    float* spf = (float*)(sm0 + DF_PB);

    int t = threadIdx.x, wid = t >> 5, lid = t & 31;
    int mwid = wid & 3, nhalf = wid >> 2;
    int h = blockIdx.x, b = blockIdx.y;

    uint32_t aRowSel = (lid & 7) + ((lid >> 3) & 1) * 8;
    uint32_t aColSel = ((lid >> 4) & 1) * 16;
    uint32_t swz = (lid & 7) * 16;

    const float4* xb4 = (const float4*)(g_xt + (size_t)b*PIX*CC);

    float acc[32];
#pragma unroll
    for (int i = 0; i < 32; i++) acc[i] = 0.f;

#define DF_PARAMS(kk_, psel_) do {                                               \
    if (t < 128) {                                                               \
        int px_ = t;                                                             \
        int pix_ = h*WW + px_;                                                   \
        float oy_ = g_offset[((size_t)(b*18 + 2*(kk_)  ))*PIX + pix_];           \
        float ox_ = g_offset[((size_t)(b*18 + 2*(kk_)+1))*PIX + pix_];           \
        float m_  = g_mask  [((size_t)(b*9  + (kk_)    ))*PIX + pix_];           \
        int ky_ = (kk_)/3, kx_ = (kk_) - ky_*3;                                  \
        float py_  = oy_ + (float)(ky_ + h - 1);                                 \
        float pxf_ = ox_ + (float)(kx_ + px_ - 1);                               \
        float y0f_ = floorf(py_), x0f_ = floorf(pxf_);                           \
        int y0_ = (int)y0f_, x0_ = (int)x0f_;                                    \
        int y1_ = y0_ + 1,   x1_ = x0_ + 1;                                      \
        float wy1_ = py_ - y0f_,  wx1_ = pxf_ - x0f_;                            \
        float wy0_ = 1.f - wy1_, wx0_ = 1.f - wx1_;                              \
        bool vy0_ = (y0_>=0 && y0_<HH), vy1_ = (y1_>=0 && y1_<HH);               \
        bool vx0_ = (x0_>=0 && x0_<WW), vx1_ = (x1_>=0 && x1_<WW);               \
        int y0c_ = min(max(y0_,0),HH-1), y1c_ = min(max(y1_,0),HH-1);            \
        int x0c_ = min(max(x0_,0),WW-1), x1c_ = min(max(x1_,0),WW-1);            \
        int base_ = (psel_)*1024 + px_*8;                                        \
        spi[base_+0] = (y0c_*WW + x0c_)*16;                                      \
        spi[base_+1] = (y0c_*WW + x1c_)*16;                                      \
        spi[base_+2] = (y1c_*WW + x0c_)*16;                                      \
        spi[base_+3] = (y1c_*WW + x1c_)*16;                                      \
        spf[base_+4] = (vy0_&&vx0_) ? wy0_*wx0_*m_ : 0.f;                        \
        spf[base_+5] = (vy0_&&vx1_) ? wy0_*wx1_*m_ : 0.f;                        \
        spf[base_+6] = (vy1_&&vx0_) ? wy1_*wx0_*m_ : 0.f;                        \
        spf[base_+7] = (vy1_&&vx1_) ? wy1_*wx1_*m_ : 0.f;                        \
    } } while(0)

#define DF_GATHER(psel_, dH_) do {                                               \
    _Pragma("unroll")                                                            \
    for (int it_ = 0; it_ < 8; it_++) {                                          \
        int j_ = it_*256 + t;                                                    \
        int px_ = j_ >> 4, l16_ = j_ & 15;                                       \
        int base_ = (psel_)*1024 + px_*8;                                        \
        int i00 = spi[base_+0], i01 = spi[base_+1], i10 = spi[base_+2], i11 = spi[base_+3]; \
        float g00 = spf[base_+4], g01 = spf[base_+5], g10 = spf[base_+6], g11 = spf[base_+7]; \
        float4 a_ = xb4[i00 + l16_];                                             \
        float4 c_ = xb4[i01 + l16_];                                             \
        float4 d_ = xb4[i10 + l16_];                                             \
        float4 e_ = xb4[i11 + l16_];                                             \
        float v0 = g00*a_.x + g01*c_.x + g10*d_.x + g11*e_.x;                    \
        float v1 = g00*a_.y + g01*c_.y + g10*d_.y + g11*e_.y;                    \
        float v2 = g00*a_.z + g01*c_.z + g10*d_.z + g11*e_.z;                    \
        float v3 = g00*a_.w + g01*c_.w + g10*d_.w + g11*e_.w;                    \
        uint32_t off_ = px_*128 + ((l16_*8) ^ ((px_ & 7)*16));                   \
        sts2(sb + (dH_) + off_, pk16(v0,v1), pk16(v2,v3));                       \
    } } while(0)

    // prologue
    DF_PARAMS(0, 0);
    __syncthreads();
    DF_GATHER(0, DF_A0);
    DF_PARAMS(1, 1);
    __syncthreads();

    for (int kk = 0; kk < 9; kk++) {
        int cs = kk & 1, ns = cs ^ 1;
        if (kk < 8) {
            if (ns) DF_GATHER(1, DF_A1);
            else    DF_GATHER(0, DF_A0);
        }
        if (kk < 7) DF_PARAMS(kk+2, cs);

        uint32_t aH = sb + (cs ? DF_A1 : DF_A0);
#pragma unroll
        for (int ks = 0; ks < 4; ks++) {
            int bi = (kk*16 + ks*4 + nhalf*2)*32 + lid;
            uint32_t ah[8];
#pragma unroll
            for (int m = 0; m < 2; m++) {
                uint32_t R = mwid*32 + m*16 + aRowSel;
                uint32_t aa = aH + R*128 + ((ks*32 + aColSel) ^ swz);
                ldsm4(ah[m*4+0], ah[m*4+1], ah[m*4+2], ah[m*4+3], aa);
            }
            { // first N-16 half
                uint4 BH = g_dBh[bi], BL = g_dBl[bi];
#pragma unroll
                for (int m = 0; m < 2; m++) {
                    float* d0 = acc + (m*4+0)*4;
                    float* d1 = acc + (m*4+1)*4;
                    mma16816(d0, ah[m*4+0],ah[m*4+1],ah[m*4+2],ah[m*4+3], BH.x, BH.y);
                    mma16816(d0, ah[m*4+0],ah[m*4+1],ah[m*4+2],ah[m*4+3], BL.x, BL.y);
                    mma16816(d1, ah[m*4+0],ah[m*4+1],ah[m*4+2],ah[m*4+3], BH.z, BH.w);
                    mma16816(d1, ah[m*4+0],ah[m*4+1],ah[m*4+2],ah[m*4+3], BL.z, BL.w);
                }
            }
            { // second N-16 half
                uint4 BH = g_dBh[bi + 32], BL = g_dBl[bi + 32];
#pragma unroll
                for (int m = 0; m < 2; m++) {
                    float* d2 = acc + (m*4+2)*4;
                    float* d3 = acc + (m*4+3)*4;
                    mma16816(d2, ah[m*4+0],ah[m*4+1],ah[m*4+2],ah[m*4+3], BH.x, BH.y);
                    mma16816(d2, ah[m*4+0],ah[m*4+1],ah[m*4+2],ah[m*4+3], BL.x, BL.y);
                    mma16816(d3, ah[m*4+0],ah[m*4+1],ah[m*4+2],ah[m*4+3], BH.z, BH.w);
                    mma16816(d3, ah[m*4+0],ah[m*4+1],ah[m*4+2],ah[m*4+3], BL.z, BL.w);
                }
            }
        }
        __syncthreads();
    }

    // epilogue
    int g = lid >> 2, tig = lid & 3;
    size_t ob = (size_t)b*64*PIX + (size_t)h*WW;
#pragma unroll
    for (int n = 0; n < 4; n++)
#pragma unroll
    for (int m = 0; m < 2; m++)
#pragma unroll
    for (int r = 0; r < 4; r++) {
        int px = mwid*32 + m*16 + g + (r>>1)*8;
        int oc = nhalf*32 + n*8 + 2*tig + (r&1);
        out[ob + (size_t)oc*PIX + px] = acc[(m*4+n)*4 + r];
    }
}

// ---------------------------------------------------------------------------
extern "C" void kernel_launch(void* const* d_in, const int* in_sizes, int n_in,
                              void* d_out, int out_size)
{
    const float* x     = (const float*)d_in[0];
    const float* guide = (const float*)d_in[1];
    const float* w_off = (const float*)d_in[2];
    const float* b_off = (const float*)d_in[3];
    const float* w_mod = (const float*)d_in[4];
    const float* b_mod = (const float*)d_in[5];
    const float* w_reg = (const float*)d_in[6];
    float* out = (float*)d_out;

    cudaFuncSetAttribute(k_offmod, cudaFuncAttributeMaxDynamicSharedMemorySize, OM_SMEM);
    cudaFuncSetAttribute(k_deform, cudaFuncAttributeMaxDynamicSharedMemorySize, DF_SMEM);

    k_transpose<<<dim3(HH, BB, 2), 256>>>(x, guide);
    k_prepw    <<<72, 256>>>(w_off, w_mod, w_reg);
    k_offmod   <<<dim3(HH, BB), 256, OM_SMEM>>>(b_off, b_mod);
    k_deform   <<<dim3(HH, BB), 256, DF_SMEM>>>(out);
}

// round 15
// speedup vs baseline: 1.4319x; 1.1447x over previous
#include <cuda_runtime.h>
#include <cuda_fp16.h>
#include <stdint.h>
#include <math.h>

#define BB 4
#define CC 64
#define HH 128
#define WW 128
#define OO 64
#define PIX 16384

// ---------------- device scratch ----------------
__device__ float g_offset[BB*18*PIX];
__device__ float g_mask[BB*9*PIX];
__device__ float g_xt[BB*PIX*CC];     // x NHWC
__device__ float g_gt[BB*PIX*CC];     // guide NHWC
// B weights (fp16 hi/lo) prepacked in mma fragment order
__device__ uint4 g_oBh[4608];   // offmod: (chunk*8 + ks*2 + nhalf)*32 + lane
__device__ uint4 g_oBl[4608];
__device__ uint4 g_dBh[4608];   // deform: (kk*16 + ks*4 + nhalf*2 + p)*32 + lane
__device__ uint4 g_dBl[4608];

// ---------------- helpers ----------------
__device__ __forceinline__ uint32_t smem_u32(const void* p){
    uint32_t a;
    asm("{ .reg .u64 t; cvta.to.shared.u64 t, %1; cvt.u32.u64 %0, t; }" : "=r"(a) : "l"(p));
    return a;
}
__device__ __forceinline__ void ldsm4(uint32_t& r0, uint32_t& r1, uint32_t& r2, uint32_t& r3, uint32_t a){
    asm volatile("ldmatrix.sync.aligned.m8n8.x4.shared.b16 {%0,%1,%2,%3}, [%4];"
                 : "=r"(r0),"=r"(r1),"=r"(r2),"=r"(r3) : "r"(a));
}
__device__ __forceinline__ void mma16816(float* d, uint32_t a0, uint32_t a1, uint32_t a2, uint32_t a3,
                                         uint32_t b0, uint32_t b1){
    asm volatile("mma.sync.aligned.m16n8k16.row.col.f32.f16.f16.f32 "
                 "{%0,%1,%2,%3}, {%4,%5,%6,%7}, {%8,%9}, {%0,%1,%2,%3};"
                 : "+f"(d[0]),"+f"(d[1]),"+f"(d[2]),"+f"(d[3])
                 : "r"(a0),"r"(a1),"r"(a2),"r"(a3),"r"(b0),"r"(b1));
}
__device__ __forceinline__ void sts4(uint32_t a, uint32_t x, uint32_t y, uint32_t z, uint32_t w){
    asm volatile("st.shared.v4.u32 [%0], {%1,%2,%3,%4};" :: "r"(a),"r"(x),"r"(y),"r"(z),"r"(w) : "memory");
}
__device__ __forceinline__ void sts2(uint32_t a, uint32_t x, uint32_t y){
    asm volatile("st.shared.v2.u32 [%0], {%1,%2};" :: "r"(a),"r"(x),"r"(y) : "memory");
}
__device__ __forceinline__ uint32_t pk16(float lo_e, float hi_e){
    uint32_t r;
    asm("cvt.rn.f16x2.f32 %0, %1, %2;" : "=r"(r) : "f"(hi_e), "f"(lo_e));
    return r;
}

// ---------------------------------------------------------------------------
// Kernel 0: NCHW -> NHWC transpose (x and guide), vectorized both directions
// ---------------------------------------------------------------------------
__global__ void k_transpose(const float* __restrict__ x, const float* __restrict__ g){
    __shared__ float s[64*129];
    int h = blockIdx.x, b = blockIdx.y;
    const float* src = blockIdx.z ? g : x;
    float* dst       = blockIdx.z ? g_gt : g_xt;
    const float* xp = src + ((size_t)b*CC)*PIX + (size_t)h*WW;
    for (int i = threadIdx.x; i < 2048; i += 256) {
        int c = i >> 5, x4 = (i & 31) * 4;
        float4 v = *(const float4*)(xp + (size_t)c*PIX + x4);
        s[c*129 + x4+0]=v.x; s[c*129 + x4+1]=v.y; s[c*129 + x4+2]=v.z; s[c*129 + x4+3]=v.w;
    }
    __syncthreads();
    float* op = dst + ((size_t)(b*HH + h)*WW)*CC;
    for (int i = threadIdx.x; i < 2048; i += 256) {
        int xx = i >> 4, c4 = (i & 15) * 4;
        float4 v;
        v.x = s[(c4+0)*129 + xx];
        v.y = s[(c4+1)*129 + xx];
        v.z = s[(c4+2)*129 + xx];
        v.w = s[(c4+3)*129 + xx];
        *(float4*)(op + (size_t)xx*CC + c4) = v;
    }
}

// ---------------------------------------------------------------------------
// Kernel 1: weight prep — fp32 -> fp16 hi/lo, packed in mma fragment order.
// ---------------------------------------------------------------------------
__global__ void k_prepw(const float* __restrict__ w_off, const float* __restrict__ w_mod,
                        const float* __restrict__ w_reg){
    int i = blockIdx.x*256 + threadIdx.x;
    if (i >= 18432) return;
    int q = i & 3, L = (i >> 2) & 31;
    { // offmod
        int nhalf = (i >> 7) & 1, ks = (i >> 8) & 3, chunk = i >> 10;
        int kk = chunk >> 1, half = chunk & 1;
        int oc = nhalf*16 + ((q >> 1) & 1)*8 + (L >> 2);
        int ch = ks*16 + (q & 1)*8 + (L & 3)*2;
        int c0 = half*64 + ch;
        float w0 = 0.f, w1 = 0.f;
        if (oc < 18)      { w0 = w_off[(oc*128 + c0)*9 + kk];       w1 = w_off[(oc*128 + c0 + 1)*9 + kk]; }
        else if (oc < 27) { w0 = w_mod[((oc-18)*128 + c0)*9 + kk];  w1 = w_mod[((oc-18)*128 + c0 + 1)*9 + kk]; }
        float h0 = __half2float(__float2half_rn(w0));
        float h1 = __half2float(__float2half_rn(w1));
        ((uint32_t*)g_oBh)[i] = pk16(h0, h1);
        ((uint32_t*)g_oBl)[i] = pk16(w0 - h0, w1 - h1);
    }
    { // deform
        int p = (i >> 7) & 1, nhalf = (i >> 8) & 1, ks = (i >> 9) & 3, kk = i >> 11;
        int oc = nhalf*32 + p*16 + ((q >> 1) & 1)*8 + (L >> 2);
        int ch = ks*16 + (q & 1)*8 + (L & 3)*2;
        float w0 = w_reg[(oc*64 + ch)*9 + kk], w1 = w_reg[(oc*64 + ch + 1)*9 + kk];
        float h0 = __half2float(__float2half_rn(w0));
        float h1 = __half2float(__float2half_rn(w1));
        ((uint32_t*)g_dBh)[i] = pk16(h0, h1);
        ((uint32_t*)g_dBl)[i] = pk16(w0 - h0, w1 - h1);
    }
}

// ---------------------------------------------------------------------------
// Kernel 2: offset+modulator conv (M=128, N=32(27), K=1152), HALO-STAGED.
// Per dy: stage x & guide rows (h+dy-1) with ±1 px halo (130 rows each),
// then 6 MMA chunks (3 dx x 2 src) read row-shifted views. 6 stagings vs 18.
// smem: x tile [130 rows x 128B] @0, guide tile @16640. 4 CTAs/SM.
// ---------------------------------------------------------------------------
#define OM_TILE 16640
#define OM_SMEM (33280 + 128)

__global__ __launch_bounds__(256,4) void k_offmod(const float* __restrict__ b_off,
                                                  const float* __restrict__ b_mod)
{
    extern __shared__ char smem_raw[];
    uint32_t sbr = smem_u32(smem_raw);
    uint32_t sb  = (sbr + 127) & ~127u;

    int t = threadIdx.x, wid = t >> 5, lid = t & 31;
    int mwid = wid & 3, nhalf = wid >> 2;
    int h = blockIdx.x, b = blockIdx.y;

    uint32_t aRowSel = (lid & 7) + ((lid >> 3) & 1) * 8;
    uint32_t aColSel = ((lid >> 4) & 1) * 16;

    float acc[16];
#pragma unroll
    for (int i = 0; i < 16; i++) acc[i] = 0.f;

    for (int dy = 0; dy < 3; dy++) {
        if (dy) __syncthreads();
        { // stage x & guide tiles: 130 rows (px = r-1 in [-1,128]) x 64 ch, fp16
            int hy = h + dy - 1;
            bool rowok = (hy >= 0) && (hy < HH);
            size_t rowoff = ((size_t)b*HH + (rowok ? hy : 0))*WW;
            for (int j = t; j < 2080; j += 256) {
                int src = (j >= 1040);
                int jj = src ? j - 1040 : j;
                int r = jj >> 3, c8 = jj & 7;
                int px = r - 1;
                float v0=0,v1=0,v2=0,v3=0,v4=0,v5=0,v6=0,v7=0;
                if (rowok && px >= 0 && px < WW) {
                    const float* base = (src ? g_gt : g_xt) + (rowoff + px)*CC;
                    const float4* p = (const float4*)(base + c8*8);
                    float4 a = p[0], c = p[1];
                    v0=a.x; v1=a.y; v2=a.z; v3=a.w; v4=c.x; v5=c.y; v6=c.z; v7=c.w;
                }
                uint32_t off = src*OM_TILE + r*128 + ((c8 ^ (r & 7)) * 16);
                sts4(sb + off, pk16(v0,v1), pk16(v2,v3), pk16(v4,v5), pk16(v6,v7));
            }
        }
        __syncthreads();

#pragma unroll
        for (int half = 0; half < 2; half++) {
            uint32_t tileB = sb + half*OM_TILE;
#pragma unroll
            for (int dx = 0; dx < 3; dx++) {
                int chunk = (dy*3 + dx)*2 + half;
                uint32_t swzdx = (((lid & 7) + dx) & 7) * 16;
#pragma unroll
                for (int ks = 0; ks < 4; ks++) {
                    uint4 BH = g_oBh[(chunk*8 + ks*2 + nhalf)*32 + lid];
                    uint4 BL = g_oBl[(chunk*8 + ks*2 + nhalf)*32 + lid];
                    uint32_t ah[8];
#pragma unroll
                    for (int m = 0; m < 2; m++) {
                        uint32_t R = mwid*32 + m*16 + aRowSel + dx;   // tile row = px + dx
                        uint32_t aa = tileB + R*128 + ((ks*32 + aColSel) ^ swzdx);
                        ldsm4(ah[m*4+0], ah[m*4+1], ah[m*4+2], ah[m*4+3], aa);
                    }
#pragma unroll
                    for (int m = 0; m < 2; m++) {
                        float* d0 = acc + (m*2+0)*4;
                        float* d1 = acc + (m*2+1)*4;
                        mma16816(d0, ah[m*4+0],ah[m*4+1],ah[m*4+2],ah[m*4+3], BH.x, BH.y);
                        mma16816(d0, ah[m*4+0],ah[m*4+1],ah[m*4+2],ah[m*4+3], BL.x, BL.y);
                        mma16816(d1, ah[m*4+0],ah[m*4+1],ah[m*4+2],ah[m*4+3], BH.z, BH.w);
                        mma16816(d1, ah[m*4+0],ah[m*4+1],ah[m*4+2],ah[m*4+3], BL.z, BL.w);
                    }
                }
            }
        }
    }

    // epilogue
    int g = lid >> 2, tig = lid & 3;
    int pixbase = h*WW;
#pragma unroll
    for (int m = 0; m < 2; m++)
#pragma unroll
    for (int n = 0; n < 2; n++)
#pragma unroll
    for (int r = 0; r < 4; r++) {
        int px = mwid*32 + m*16 + g + (r>>1)*8;
        int oc = nhalf*16 + n*8 + 2*tig + (r&1);
        float v = acc[(m*2+n)*4 + r];
        int pix = pixbase + px;
        if (oc < 18) {
            g_offset[(size_t)(b*18 + oc)*PIX + pix] = v + b_off[oc];
        } else if (oc < 27) {
            float z = v + b_mod[oc-18];
            g_mask[(size_t)(b*9 + oc-18)*PIX + pix] = 2.f / (1.f + expf(-z));
        }
    }
}

// ---------------------------------------------------------------------------
// Kernel 3: deformable conv (M=128, N=64, K=576), pipelined fp16 2-term.
// 4 CTAs/SM (single wave). B consumed in two halves. (R14, proven)
// ---------------------------------------------------------------------------
#define DF_PB  0
#define DF_A0  8192
#define DF_A1  24576
#define DF_SMEM (40960 + 128)

__global__ __launch_bounds__(256,4) void k_deform(float* __restrict__ out)
{
    extern __shared__ char smem_raw[];
    uint32_t sbr = smem_u32(smem_raw);
    uint32_t sb  = (sbr + 127) & ~127u;
    char* sm0 = smem_raw + (sb - sbr);
    int*   spi = (int*)(sm0 + DF_PB);
    float* spf = (float*)(sm0 + DF_PB);

    int t = threadIdx.x, wid = t >> 5, lid = t & 31;
    int mwid = wid & 3, nhalf = wid >> 2;
    int h = blockIdx.x, b = blockIdx.y;

    uint32_t aRowSel = (lid & 7) + ((lid >> 3) & 1) * 8;
    uint32_t aColSel = ((lid >> 4) & 1) * 16;
    uint32_t swz = (lid & 7) * 16;

    const float4* xb4 = (const float4*)(g_xt + (size_t)b*PIX*CC);

    float acc[32];
#pragma unroll
    for (int i = 0; i < 32; i++) acc[i] = 0.f;

#define DF_PARAMS(kk_, psel_) do {                                               \
    if (t < 128) {                                                               \
        int px_ = t;                                                             \
        int pix_ = h*WW + px_;                                                   \
        float oy_ = g_offset[((size_t)(b*18 + 2*(kk_)  ))*PIX + pix_];           \
        float ox_ = g_offset[((size_t)(b*18 + 2*(kk_)+1))*PIX + pix_];           \
        float m_  = g_mask  [((size_t)(b*9  + (kk_)    ))*PIX + pix_];           \
        int ky_ = (kk_)/3, kx_ = (kk_) - ky_*3;                                  \
        float py_  = oy_ + (float)(ky_ + h - 1);                                 \
        float pxf_ = ox_ + (float)(kx_ + px_ - 1);                               \
        float y0f_ = floorf(py_), x0f_ = floorf(pxf_);                           \
        int y0_ = (int)y0f_, x0_ = (int)x0f_;                                    \
        int y1_ = y0_ + 1,   x1_ = x0_ + 1;                                      \
        float wy1_ = py_ - y0f_,  wx1_ = pxf_ - x0f_;                            \
        float wy0_ = 1.f - wy1_, wx0_ = 1.f - wx1_;                              \
        bool vy0_ = (y0_>=0 && y0_<HH), vy1_ = (y1_>=0 && y1_<HH);               \
        bool vx0_ = (x0_>=0 && x0_<WW), vx1_ = (x1_>=0 && x1_<WW);               \
        int y0c_ = min(max(y0_,0),HH-1), y1c_ = min(max(y1_,0),HH-1);            \
        int x0c_ = min(max(x0_,0),WW-1), x1c_ = min(max(x1_,0),WW-1);            \
        int base_ = (psel_)*1024 + px_*8;                                        \
        spi[base_+0] = (y0c_*WW + x0c_)*16;                                      \
        spi[base_+1] = (y0c_*WW + x1c_)*16;                                      \
        spi[base_+2] = (y1c_*WW + x0c_)*16;                                      \
        spi[base_+3] = (y1c_*WW + x1c_)*16;                                      \
        spf[base_+4] = (vy0_&&vx0_) ? wy0_*wx0_*m_ : 0.f;                        \
        spf[base_+5] = (vy0_&&vx1_) ? wy0_*wx1_*m_ : 0.f;                        \
        spf[base_+6] = (vy1_&&vx0_) ? wy1_*wx0_*m_ : 0.f;                        \
        spf[base_+7] = (vy1_&&vx1_) ? wy1_*wx1_*m_ : 0.f;                        \
    } } while(0)

#define DF_GATHER(psel_, dH_) do {                                               \
    _Pragma("unroll")                                                            \
    for (int it_ = 0; it_ < 8; it_++) {                                          \
        int j_ = it_*256 + t;                                                    \
        int px_ = j_ >> 4, l16_ = j_ & 15;                                       \
        int base_ = (psel_)*1024 + px_*8;                                        \
        int i00 = spi[base_+0], i01 = spi[base_+1], i10 = spi[base_+2], i11 = spi[base_+3]; \
        float g00 = spf[base_+4], g01 = spf[base_+5], g10 = spf[base_+6], g11 = spf[base_+7]; \
        float4 a_ = xb4[i00 + l16_];                                             \
        float4 c_ = xb4[i01 + l16_];                                             \
        float4 d_ = xb4[i10 + l16_];                                             \
        float4 e_ = xb4[i11 + l16_];                                             \
        float v0 = g00*a_.x + g01*c_.x + g10*d_.x + g11*e_.x;                    \
        float v1 = g00*a_.y + g01*c_.y + g10*d_.y + g11*e_.y;                    \
        float v2 = g00*a_.z + g01*c_.z + g10*d_.z + g11*e_.z;                    \
        float v3 = g00*a_.w + g01*c_.w + g10*d_.w + g11*e_.w;                    \
        uint32_t off_ = px_*128 + ((l16_*8) ^ ((px_ & 7)*16));                   \
        sts2(sb + (dH_) + off_, pk16(v0,v1), pk16(v2,v3));                       \
    } } while(0)

    // prologue
    DF_PARAMS(0, 0);
    __syncthreads();
    DF_GATHER(0, DF_A0);
    DF_PARAMS(1, 1);
    __syncthreads();

    for (int kk = 0; kk < 9; kk++) {
        int cs = kk & 1, ns = cs ^ 1;
        if (kk < 8) {
            if (ns) DF_GATHER(1, DF_A1);
            else    DF_GATHER(0, DF_A0);
        }
        if (kk < 7) DF_PARAMS(kk+2, cs);

        uint32_t aH = sb + (cs ? DF_A1 : DF_A0);
#pragma unroll
        for (int ks = 0; ks < 4; ks++) {
            int bi = (kk*16 + ks*4 + nhalf*2)*32 + lid;
            uint32_t ah[8];
#pragma unroll
            for (int m = 0; m < 2; m++) {
                uint32_t R = mwid*32 + m*16 + aRowSel;
                uint32_t aa = aH + R*128 + ((ks*32 + aColSel) ^ swz);
                ldsm4(ah[m*4+0], ah[m*4+1], ah[m*4+2], ah[m*4+3], aa);
            }
            { // first N-16 half
                uint4 BH = g_dBh[bi], BL = g_dBl[bi];
#pragma unroll
                for (int m = 0; m < 2; m++) {
                    float* d0 = acc + (m*4+0)*4;
                    float* d1 = acc + (m*4+1)*4;
                    mma16816(d0, ah[m*4+0],ah[m*4+1],ah[m*4+2],ah[m*4+3], BH.x, BH.y);
                    mma16816(d0, ah[m*4+0],ah[m*4+1],ah[m*4+2],ah[m*4+3], BL.x, BL.y);
                    mma16816(d1, ah[m*4+0],ah[m*4+1],ah[m*4+2],ah[m*4+3], BH.z, BH.w);
                    mma16816(d1, ah[m*4+0],ah[m*4+1],ah[m*4+2],ah[m*4+3], BL.z, BL.w);
                }
            }
            { // second N-16 half
                uint4 BH = g_dBh[bi + 32], BL = g_dBl[bi + 32];
#pragma unroll
                for (int m = 0; m < 2; m++) {
                    float* d2 = acc + (m*4+2)*4;
                    float* d3 = acc + (m*4+3)*4;
                    mma16816(d2, ah[m*4+0],ah[m*4+1],ah[m*4+2],ah[m*4+3], BH.x, BH.y);
                    mma16816(d2, ah[m*4+0],ah[m*4+1],ah[m*4+2],ah[m*4+3], BL.x, BL.y);
                    mma16816(d3, ah[m*4+0],ah[m*4+1],ah[m*4+2],ah[m*4+3], BH.z, BH.w);
                    mma16816(d3, ah[m*4+0],ah[m*4+1],ah[m*4+2],ah[m*4+3], BL.z, BL.w);
                }
            }
        }
        __syncthreads();
    }

    // epilogue
    int g = lid >> 2, tig = lid & 3;
    size_t ob = (size_t)b*64*PIX + (size_t)h*WW;
#pragma unroll
    for (int n = 0; n < 4; n++)
#pragma unroll
    for (int m = 0; m < 2; m++)
#pragma unroll
    for (int r = 0; r < 4; r++) {
        int px = mwid*32 + m*16 + g + (r>>1)*8;
        int oc = nhalf*32 + n*8 + 2*tig + (r&1);
        out[ob + (size_t)oc*PIX + px] = acc[(m*4+n)*4 + r];
    }
}

// ---------------------------------------------------------------------------
extern "C" void kernel_launch(void* const* d_in, const int* in_sizes, int n_in,
                              void* d_out, int out_size)
{
    const float* x     = (const float*)d_in[0];
    const float* guide = (const float*)d_in[1];
    const float* w_off = (const float*)d_in[2];
    const float* b_off = (const float*)d_in[3];
    const float* w_mod = (const float*)d_in[4];
    const float* b_mod = (const float*)d_in[5];
    const float* w_reg = (const float*)d_in[6];
    float* out = (float*)d_out;

    cudaFuncSetAttribute(k_offmod, cudaFuncAttributeMaxDynamicSharedMemorySize, OM_SMEM);
    cudaFuncSetAttribute(k_deform, cudaFuncAttributeMaxDynamicSharedMemorySize, DF_SMEM);

    k_transpose<<<dim3(HH, BB, 2), 256>>>(x, guide);
    k_prepw    <<<72, 256>>>(w_off, w_mod, w_reg);
    k_offmod   <<<dim3(HH, BB), 256, OM_SMEM>>>(b_off, b_mod);
    k_deform   <<<dim3(HH, BB), 256, DF_SMEM>>>(out);
}

// round 16
// speedup vs baseline: 1.7524x; 1.2238x over previous
#include <cuda_runtime.h>
#include <cuda_fp16.h>
#include <stdint.h>
#include <math.h>

#define BB 4
#define CC 64
#define HH 128
#define WW 128
#define OO 64
#define PIX 16384

// ---------------- device scratch ----------------
__device__ float g_offset[BB*18*PIX];
__device__ float g_mask[BB*9*PIX];
__device__ __half g_xt[BB*PIX*CC];    // x NHWC fp16
__device__ __half g_gt[BB*PIX*CC];    // guide NHWC fp16
// B weights (fp16 hi/lo) prepacked in mma fragment order
__device__ uint4 g_oBh[4608];   // offmod: (chunk*8 + ks*2 + nhalf)*32 + lane
__device__ uint4 g_oBl[4608];
__device__ uint4 g_dBh[4608];   // deform: (kk*16 + ks*4 + nhalf*2 + p)*32 + lane
__device__ uint4 g_dBl[4608];

// ---------------- helpers ----------------
__device__ __forceinline__ uint32_t smem_u32(const void* p){
    uint32_t a;
    asm("{ .reg .u64 t; cvta.to.shared.u64 t, %1; cvt.u32.u64 %0, t; }" : "=r"(a) : "l"(p));
    return a;
}
__device__ __forceinline__ void ldsm4(uint32_t& r0, uint32_t& r1, uint32_t& r2, uint32_t& r3, uint32_t a){
    asm volatile("ldmatrix.sync.aligned.m8n8.x4.shared.b16 {%0,%1,%2,%3}, [%4];"
                 : "=r"(r0),"=r"(r1),"=r"(r2),"=r"(r3) : "r"(a));
}
__device__ __forceinline__ void mma16816(float* d, uint32_t a0, uint32_t a1, uint32_t a2, uint32_t a3,
                                         uint32_t b0, uint32_t b1){
    asm volatile("mma.sync.aligned.m16n8k16.row.col.f32.f16.f16.f32 "
                 "{%0,%1,%2,%3}, {%4,%5,%6,%7}, {%8,%9}, {%0,%1,%2,%3};"
                 : "+f"(d[0]),"+f"(d[1]),"+f"(d[2]),"+f"(d[3])
                 : "r"(a0),"r"(a1),"r"(a2),"r"(a3),"r"(b0),"r"(b1));
}
__device__ __forceinline__ void sts4(uint32_t a, uint32_t x, uint32_t y, uint32_t z, uint32_t w){
    asm volatile("st.shared.v4.u32 [%0], {%1,%2,%3,%4};" :: "r"(a),"r"(x),"r"(y),"r"(z),"r"(w) : "memory");
}
__device__ __forceinline__ uint32_t pk16(float lo_e, float hi_e){
    uint32_t r;
    asm("cvt.rn.f16x2.f32 %0, %1, %2;" : "=r"(r) : "f"(hi_e), "f"(lo_e));
    return r;
}
__device__ __forceinline__ float2 h2f(uint32_t u){
    __half2 h = *reinterpret_cast<__half2*>(&u);
    return __half22float2(h);
}

// ---------------------------------------------------------------------------
// Kernel 0: NCHW fp32 -> NHWC fp16 transpose (x and guide)
// ---------------------------------------------------------------------------
__global__ void k_transpose(const float* __restrict__ x, const float* __restrict__ g){
    __shared__ float s[64*129];
    int h = blockIdx.x, b = blockIdx.y;
    const float* src = blockIdx.z ? g : x;
    __half* dst      = blockIdx.z ? g_gt : g_xt;
    const float* xp = src + ((size_t)b*CC)*PIX + (size_t)h*WW;
    for (int i = threadIdx.x; i < 2048; i += 256) {
        int c = i >> 5, x4 = (i & 31) * 4;
        float4 v = *(const float4*)(xp + (size_t)c*PIX + x4);
        s[c*129 + x4+0]=v.x; s[c*129 + x4+1]=v.y; s[c*129 + x4+2]=v.z; s[c*129 + x4+3]=v.w;
    }
    __syncthreads();
    __half* op = dst + ((size_t)(b*HH + h)*WW)*CC;
    for (int i = threadIdx.x; i < 2048; i += 256) {
        int xx = i >> 4, c4 = (i & 15) * 4;
        uint2 o;
        o.x = pk16(s[(c4+0)*129 + xx], s[(c4+1)*129 + xx]);
        o.y = pk16(s[(c4+2)*129 + xx], s[(c4+3)*129 + xx]);
        *(uint2*)(op + (size_t)xx*CC + c4) = o;
    }
}

// ---------------------------------------------------------------------------
// Kernel 1: weight prep — fp32 -> fp16 hi/lo, packed in mma fragment order.
// ---------------------------------------------------------------------------
__global__ void k_prepw(const float* __restrict__ w_off, const float* __restrict__ w_mod,
                        const float* __restrict__ w_reg){
    int i = blockIdx.x*256 + threadIdx.x;
    if (i >= 18432) return;
    int q = i & 3, L = (i >> 2) & 31;
    { // offmod
        int nhalf = (i >> 7) & 1, ks = (i >> 8) & 3, chunk = i >> 10;
        int kk = chunk >> 1, half = chunk & 1;
        int oc = nhalf*16 + ((q >> 1) & 1)*8 + (L >> 2);
        int ch = ks*16 + (q & 1)*8 + (L & 3)*2;
        int c0 = half*64 + ch;
        float w0 = 0.f, w1 = 0.f;
        if (oc < 18)      { w0 = w_off[(oc*128 + c0)*9 + kk];       w1 = w_off[(oc*128 + c0 + 1)*9 + kk]; }
        else if (oc < 27) { w0 = w_mod[((oc-18)*128 + c0)*9 + kk];  w1 = w_mod[((oc-18)*128 + c0 + 1)*9 + kk]; }
        float h0 = __half2float(__float2half_rn(w0));
        float h1 = __half2float(__float2half_rn(w1));
        ((uint32_t*)g_oBh)[i] = pk16(h0, h1);
        ((uint32_t*)g_oBl)[i] = pk16(w0 - h0, w1 - h1);
    }
    { // deform
        int p = (i >> 7) & 1, nhalf = (i >> 8) & 1, ks = (i >> 9) & 3, kk = i >> 11;
        int oc = nhalf*32 + p*16 + ((q >> 1) & 1)*8 + (L >> 2);
        int ch = ks*16 + (q & 1)*8 + (L & 3)*2;
        float w0 = w_reg[(oc*64 + ch)*9 + kk], w1 = w_reg[(oc*64 + ch + 1)*9 + kk];
        float h0 = __half2float(__float2half_rn(w0));
        float h1 = __half2float(__float2half_rn(w1));
        ((uint32_t*)g_dBh)[i] = pk16(h0, h1);
        ((uint32_t*)g_dBl)[i] = pk16(w0 - h0, w1 - h1);
    }
}

// ---------------------------------------------------------------------------
// Kernel 2: offset+modulator conv (M=128, N=32(27), K=1152), HALO-STAGED.
// fp16 sources -> staging is pure uint4 copy. 4 CTAs/SM.
// ---------------------------------------------------------------------------
#define OM_TILE 16640
#define OM_SMEM (33280 + 128)

__global__ __launch_bounds__(256,4) void k_offmod(const float* __restrict__ b_off,
                                                  const float* __restrict__ b_mod)
{
    extern __shared__ char smem_raw[];
    uint32_t sbr = smem_u32(smem_raw);
    uint32_t sb  = (sbr + 127) & ~127u;

    int t = threadIdx.x, wid = t >> 5, lid = t & 31;
    int mwid = wid & 3, nhalf = wid >> 2;
    int h = blockIdx.x, b = blockIdx.y;

    uint32_t aRowSel = (lid & 7) + ((lid >> 3) & 1) * 8;
    uint32_t aColSel = ((lid >> 4) & 1) * 16;

    float acc[16];
#pragma unroll
    for (int i = 0; i < 16; i++) acc[i] = 0.f;

    const uint4* xb = (const uint4*)g_xt;
    const uint4* gb = (const uint4*)g_gt;

    for (int dy = 0; dy < 3; dy++) {
        if (dy) __syncthreads();
        { // stage x & guide tiles: 130 rows (px = r-1) x 64 ch fp16 (8 uint4/row)
            int hy = h + dy - 1;
            bool rowok = (hy >= 0) && (hy < HH);
            size_t rowoff = ((size_t)b*HH + (rowok ? hy : 0))*WW;
            for (int j = t; j < 2080; j += 256) {
                int src = (j >= 1040);
                int jj = src ? j - 1040 : j;
                int r = jj >> 3, c8 = jj & 7;
                int px = r - 1;
                uint4 v = make_uint4(0,0,0,0);
                if (rowok && px >= 0 && px < WW) {
                    const uint4* bp = src ? gb : xb;
                    v = bp[(rowoff + px)*8 + c8];
                }
                uint32_t off = src*OM_TILE + r*128 + ((c8 ^ (r & 7)) * 16);
                sts4(sb + off, v.x, v.y, v.z, v.w);
            }
        }
        __syncthreads();

#pragma unroll
        for (int half = 0; half < 2; half++) {
            uint32_t tileB = sb + half*OM_TILE;
#pragma unroll
            for (int dx = 0; dx < 3; dx++) {
                int chunk = (dy*3 + dx)*2 + half;
                uint32_t swzdx = (((lid & 7) + dx) & 7) * 16;
#pragma unroll
                for (int ks = 0; ks < 4; ks++) {
                    uint4 BH = g_oBh[(chunk*8 + ks*2 + nhalf)*32 + lid];
                    uint4 BL = g_oBl[(chunk*8 + ks*2 + nhalf)*32 + lid];
                    uint32_t ah[8];
#pragma unroll
                    for (int m = 0; m < 2; m++) {
                        uint32_t R = mwid*32 + m*16 + aRowSel + dx;   // tile row = px + dx
                        uint32_t aa = tileB + R*128 + ((ks*32 + aColSel) ^ swzdx);
                        ldsm4(ah[m*4+0], ah[m*4+1], ah[m*4+2], ah[m*4+3], aa);
                    }
#pragma unroll
                    for (int m = 0; m < 2; m++) {
                        float* d0 = acc + (m*2+0)*4;
                        float* d1 = acc + (m*2+1)*4;
                        mma16816(d0, ah[m*4+0],ah[m*4+1],ah[m*4+2],ah[m*4+3], BH.x, BH.y);
                        mma16816(d0, ah[m*4+0],ah[m*4+1],ah[m*4+2],ah[m*4+3], BL.x, BL.y);
                        mma16816(d1, ah[m*4+0],ah[m*4+1],ah[m*4+2],ah[m*4+3], BH.z, BH.w);
                        mma16816(d1, ah[m*4+0],ah[m*4+1],ah[m*4+2],ah[m*4+3], BL.z, BL.w);
                    }
                }
            }
        }
    }

    // epilogue
    int g = lid >> 2, tig = lid & 3;
    int pixbase = h*WW;
#pragma unroll
    for (int m = 0; m < 2; m++)
#pragma unroll
    for (int n = 0; n < 2; n++)
#pragma unroll
    for (int r = 0; r < 4; r++) {
        int px = mwid*32 + m*16 + g + (r>>1)*8;
        int oc = nhalf*16 + n*8 + 2*tig + (r&1);
        float v = acc[(m*2+n)*4 + r];
        int pix = pixbase + px;
        if (oc < 18) {
            g_offset[(size_t)(b*18 + oc)*PIX + pix] = v + b_off[oc];
        } else if (oc < 27) {
            float z = v + b_mod[oc-18];
            g_mask[(size_t)(b*9 + oc-18)*PIX + pix] = 2.f / (1.f + expf(-z));
        }
    }
}

// ---------------------------------------------------------------------------
// Kernel 3: deformable conv (M=128, N=64, K=576), pipelined fp16 2-term.
// Gather from fp16 NHWC: 8 lanes/px, 8 ch/lane (uint4) — half the L1 traffic.
// 4 CTAs/SM single wave. B consumed in two halves.
// ---------------------------------------------------------------------------
#define DF_PB  0
#define DF_A0  8192
#define DF_A1  24576
#define DF_SMEM (40960 + 128)

__global__ __launch_bounds__(256,4) void k_deform(float* __restrict__ out)
{
    extern __shared__ char smem_raw[];
    uint32_t sbr = smem_u32(smem_raw);
    uint32_t sb  = (sbr + 127) & ~127u;
    char* sm0 = smem_raw + (sb - sbr);
    int*   spi = (int*)(sm0 + DF_PB);
    float* spf = (float*)(sm0 + DF_PB);

    int t = threadIdx.x, wid = t >> 5, lid = t & 31;
    int mwid = wid & 3, nhalf = wid >> 2;
    int h = blockIdx.x, b = blockIdx.y;

    uint32_t aRowSel = (lid & 7) + ((lid >> 3) & 1) * 8;
    uint32_t aColSel = ((lid >> 4) & 1) * 16;
    uint32_t swz = (lid & 7) * 16;

    const uint4* xb = (const uint4*)(g_xt + (size_t)b*PIX*CC);

    float acc[32];
#pragma unroll
    for (int i = 0; i < 32; i++) acc[i] = 0.f;

#define DF_PARAMS(kk_, psel_) do {                                               \
    if (t < 128) {                                                               \
        int px_ = t;                                                              \
        int pix_ = h*WW + px_;                                                    \
        float oy_ = g_offset[((size_t)(b*18 + 2*(kk_)  ))*PIX + pix_];            \
        float ox_ = g_offset[((size_t)(b*18 + 2*(kk_)+1))*PIX + pix_];            \
        float m_  = g_mask  [((size_t)(b*9  + (kk_)    ))*PIX + pix_];            \
        int ky_ = (kk_)/3, kx_ = (kk_) - ky_*3;                                   \
        float py_  = oy_ + (float)(ky_ + h - 1);                                  \
        float pxf_ = ox_ + (float)(kx_ + px_ - 1);                                \
        float y0f_ = floorf(py_), x0f_ = floorf(pxf_);                            \
        int y0_ = (int)y0f_, x0_ = (int)x0f_;                                     \
        int y1_ = y0_ + 1,   x1_ = x0_ + 1;                                       \
        float wy1_ = py_ - y0f_,  wx1_ = pxf_ - x0f_;                             \
        float wy0_ = 1.f - wy1_, wx0_ = 1.f - wx1_;                               \
        bool vy0_ = (y0_>=0 && y0_<HH), vy1_ = (y1_>=0 && y1_<HH);                \
        bool vx0_ = (x0_>=0 && x0_<WW), vx1_ = (x1_>=0 && x1_<WW);                \
        int y0c_ = min(max(y0_,0),HH-1), y1c_ = min(max(y1_,0),HH-1);             \
        int x0c_ = min(max(x0_,0),WW-1), x1c_ = min(max(x1_,0),WW-1);             \
        int base_ = (psel_)*1024 + px_*8;                                         \
        spi[base_+0] = (y0c_*WW + x0c_)*8;                                        \
        spi[base_+1] = (y0c_*WW + x1c_)*8;                                        \
        spi[base_+2] = (y1c_*WW + x0c_)*8;                                        \
        spi[base_+3] = (y1c_*WW + x1c_)*8;                                        \
        spf[base_+4] = (vy0_&&vx0_) ? wy0_*wx0_*m_ : 0.f;                         \
        spf[base_+5] = (vy0_&&vx1_) ? wy0_*wx1_*m_ : 0.f;                         \
        spf[base_+6] = (vy1_&&vx0_) ? wy1_*wx0_*m_ : 0.f;                         \
        spf[base_+7] = (vy1_&&vx1_) ? wy1_*wx1_*m_ : 0.f;                         \
    } } while(0)

// gather: 128px x 8 lanes (8 ch each as uint4) = 1024 tasks, 4 iters
#define DF_GATHER(psel_, dH_) do {                                               \
    _Pragma("unroll")                                                            \
    for (int it_ = 0; it_ < 4; it_++) {                                          \
        int j_ = it_*256 + t;                                                    \
        int px_ = j_ >> 3, l8_ = j_ & 7;                                         \
        int base_ = (psel_)*1024 + px_*8;                                        \
        int i00 = spi[base_+0], i01 = spi[base_+1], i10 = spi[base_+2], i11 = spi[base_+3]; \
        float g00 = spf[base_+4], g01 = spf[base_+5], g10 = spf[base_+6], g11 = spf[base_+7]; \
        uint4 A_ = xb[i00 + l8_];                                                 \
        uint4 C_ = xb[i01 + l8_];                                                 \
        uint4 D_ = xb[i10 + l8_];                                                 \
        uint4 E_ = xb[i11 + l8_];                                                 \
        float v0,v1,v2,v3,v4,v5,v6,v7;                                            \
        { float2 a0=h2f(A_.x),c0=h2f(C_.x),d0=h2f(D_.x),e0=h2f(E_.x);             \
          v0 = g00*a0.x + g01*c0.x + g10*d0.x + g11*e0.x;                         \
          v1 = g00*a0.y + g01*c0.y + g10*d0.y + g11*e0.y; }                       \
        { float2 a1=h2f(A_.y),c1=h2f(C_.y),d1=h2f(D_.y),e1=h2f(E_.y);             \
          v2 = g00*a1.x + g01*c1.x + g10*d1.x + g11*e1.x;                         \
          v3 = g00*a1.y + g01*c1.y + g10*d1.y + g11*e1.y; }                       \
        { float2 a2=h2f(A_.z),c2=h2f(C_.z),d2=h2f(D_.z),e2=h2f(E_.z);             \
          v4 = g00*a2.x + g01*c2.x + g10*d2.x + g11*e2.x;                         \
          v5 = g00*a2.y + g01*c2.y + g10*d2.y + g11*e2.y; }                       \
        { float2 a3=h2f(A_.w),c3=h2f(C_.w),d3=h2f(D_.w),e3=h2f(E_.w);             \
          v6 = g00*a3.x + g01*c3.x + g10*d3.x + g11*e3.x;                         \
          v7 = g00*a3.y + g01*c3.y + g10*d3.y + g11*e3.y; }                       \
        uint32_t off_ = px_*128 + ((l8_*16) ^ ((px_ & 7)*16));                    \
        sts4(sb + (dH_) + off_, pk16(v0,v1), pk16(v2,v3), pk16(v4,v5), pk16(v6,v7)); \
    } } while(0)

    // prologue
    DF_PARAMS(0, 0);
    __syncthreads();
    DF_GATHER(0, DF_A0);
    DF_PARAMS(1, 1);
    __syncthreads();

    for (int kk = 0; kk < 9; kk++) {
        int cs = kk & 1, ns = cs ^ 1;
        if (kk < 8) {
            if (ns) DF_GATHER(1, DF_A1);
            else    DF_GATHER(0, DF_A0);
        }
        if (kk < 7) DF_PARAMS(kk+2, cs);

        uint32_t aH = sb + (cs ? DF_A1 : DF_A0);
#pragma unroll
        for (int ks = 0; ks < 4; ks++) {
            int bi = (kk*16 + ks*4 + nhalf*2)*32 + lid;
            uint32_t ah[8];
#pragma unroll
            for (int m = 0; m < 2; m++) {
                uint32_t R = mwid*32 + m*16 + aRowSel;
                uint32_t aa = aH + R*128 + ((ks*32 + aColSel) ^ swz);
                ldsm4(ah[m*4+0], ah[m*4+1], ah[m*4+2], ah[m*4+3], aa);
            }
            { // first N-16 half
                uint4 BH = g_dBh[bi], BL = g_dBl[bi];
#pragma unroll
                for (int m = 0; m < 2; m++) {
                    float* d0 = acc + (m*4+0)*4;
                    float* d1 = acc + (m*4+1)*4;
                    mma16816(d0, ah[m*4+0],ah[m*4+1],ah[m*4+2],ah[m*4+3], BH.x, BH.y);
                    mma16816(d0, ah[m*4+0],ah[m*4+1],ah[m*4+2],ah[m*4+3], BL.x, BL.y);
                    mma16816(d1, ah[m*4+0],ah[m*4+1],ah[m*4+2],ah[m*4+3], BH.z, BH.w);
                    mma16816(d1, ah[m*4+0],ah[m*4+1],ah[m*4+2],ah[m*4+3], BL.z, BL.w);
                }
            }
            { // second N-16 half
                uint4 BH = g_dBh[bi + 32], BL = g_dBl[bi + 32];
#pragma unroll
                for (int m = 0; m < 2; m++) {
                    float* d2 = acc + (m*4+2)*4;
                    float* d3 = acc + (m*4+3)*4;
                    mma16816(d2, ah[m*4+0],ah[m*4+1],ah[m*4+2],ah[m*4+3], BH.x, BH.y);
                    mma16816(d2, ah[m*4+0],ah[m*4+1],ah[m*4+2],ah[m*4+3], BL.x, BL.y);
                    mma16816(d3, ah[m*4+0],ah[m*4+1],ah[m*4+2],ah[m*4+3], BH.z, BH.w);
                    mma16816(d3, ah[m*4+0],ah[m*4+1],ah[m*4+2],ah[m*4+3], BL.z, BL.w);
                }
            }
        }
        __syncthreads();
    }

    // epilogue
    int g = lid >> 2, tig = lid & 3;
    size_t ob = (size_t)b*64*PIX + (size_t)h*WW;
#pragma unroll
    for (int n = 0; n < 4; n++)
#pragma unroll
    for (int m = 0; m < 2; m++)
#pragma unroll
    for (int r = 0; r < 4; r++) {
        int px = mwid*32 + m*16 + g + (r>>1)*8;
        int oc = nhalf*32 + n*8 + 2*tig + (r&1);
        out[ob + (size_t)oc*PIX + px] = acc[(m*4+n)*4 + r];
    }
}

// ---------------------------------------------------------------------------
extern "C" void kernel_launch(void* const* d_in, const int* in_sizes, int n_in,
                              void* d_out, int out_size)
{
    const float* x     = (const float*)d_in[0];
    const float* guide = (const float*)d_in[1];
    const float* w_off = (const float*)d_in[2];
    const float* b_off = (const float*)d_in[3];
    const float* w_mod = (const float*)d_in[4];
    const float* b_mod = (const float*)d_in[5];
    const float* w_reg = (const float*)d_in[6];
    float* out = (float*)d_out;

    cudaFuncSetAttribute(k_offmod, cudaFuncAttributeMaxDynamicSharedMemorySize, OM_SMEM);
    cudaFuncSetAttribute(k_deform, cudaFuncAttributeMaxDynamicSharedMemorySize, DF_SMEM);

    k_transpose<<<dim3(HH, BB, 2), 256>>>(x, guide);
    k_prepw    <<<72, 256>>>(w_off, w_mod, w_reg);
    k_offmod   <<<dim3(HH, BB), 256, OM_SMEM>>>(b_off, b_mod);
    k_deform   <<<dim3(HH, BB), 256, DF_SMEM>>>(out);
}

// round 17
// speedup vs baseline: 1.8649x; 1.0642x over previous
#include <cuda_runtime.h>
#include <cuda_fp16.h>
#include <stdint.h>
#include <math.h>

#define BB 4
#define CC 64
#define HH 128
#define WW 128
#define OO 64
#define PIX 16384

// ---------------- device scratch ----------------
__device__ float g_offset[BB*18*PIX];
__device__ float g_mask[BB*9*PIX];
__device__ __half g_xt[BB*PIX*CC];    // x NHWC fp16
__device__ __half g_gt[BB*PIX*CC];    // guide NHWC fp16
// B weights (fp16 hi/lo) prepacked in mma fragment order
__device__ uint4 g_oBh[4608];   // offmod: (chunk*8 + ks*2 + nhalf)*32 + lane
__device__ uint4 g_oBl[4608];
__device__ uint4 g_dBh[4608];   // deform: (kk*16 + ks*4 + nhalf*2 + p)*32 + lane
__device__ uint4 g_dBl[4608];

// ---------------- helpers ----------------
__device__ __forceinline__ uint32_t smem_u32(const void* p){
    uint32_t a;
    asm("{ .reg .u64 t; cvta.to.shared.u64 t, %1; cvt.u32.u64 %0, t; }" : "=r"(a) : "l"(p));
    return a;
}
__device__ __forceinline__ void ldsm4(uint32_t& r0, uint32_t& r1, uint32_t& r2, uint32_t& r3, uint32_t a){
    asm volatile("ldmatrix.sync.aligned.m8n8.x4.shared.b16 {%0,%1,%2,%3}, [%4];"
                 : "=r"(r0),"=r"(r1),"=r"(r2),"=r"(r3) : "r"(a));
}
__device__ __forceinline__ void mma16816(float* d, uint32_t a0, uint32_t a1, uint32_t a2, uint32_t a3,
                                         uint32_t b0, uint32_t b1){
    asm volatile("mma.sync.aligned.m16n8k16.row.col.f32.f16.f16.f32 "
                 "{%0,%1,%2,%3}, {%4,%5,%6,%7}, {%8,%9}, {%0,%1,%2,%3};"
                 : "+f"(d[0]),"+f"(d[1]),"+f"(d[2]),"+f"(d[3])
                 : "r"(a0),"r"(a1),"r"(a2),"r"(a3),"r"(b0),"r"(b1));
}
__device__ __forceinline__ void sts4(uint32_t a, uint32_t x, uint32_t y, uint32_t z, uint32_t w){
    asm volatile("st.shared.v4.u32 [%0], {%1,%2,%3,%4};" :: "r"(a),"r"(x),"r"(y),"r"(z),"r"(w) : "memory");
}
__device__ __forceinline__ uint32_t pk16(float lo_e, float hi_e){
    uint32_t r;
    asm("cvt.rn.f16x2.f32 %0, %1, %2;" : "=r"(r) : "f"(hi_e), "f"(lo_e));
    return r;
}
__device__ __forceinline__ uint32_t bilin2(uint32_t a, uint32_t c, uint32_t d, uint32_t e,
                                           uint32_t g00, uint32_t g01, uint32_t g10, uint32_t g11){
    __half2 r = __hmul2(*(__half2*)&g00, *(__half2*)&a);
    r = __hfma2(*(__half2*)&g01, *(__half2*)&c, r);
    r = __hfma2(*(__half2*)&g10, *(__half2*)&d, r);
    r = __hfma2(*(__half2*)&g11, *(__half2*)&e, r);
    return *(uint32_t*)&r;
}

// ---------------------------------------------------------------------------
// Kernel 0: NCHW fp32 -> NHWC fp16 transpose (x and guide)
// ---------------------------------------------------------------------------
__global__ void k_transpose(const float* __restrict__ x, const float* __restrict__ g){
    __shared__ float s[64*129];
    int h = blockIdx.x, b = blockIdx.y;
    const float* src = blockIdx.z ? g : x;
    __half* dst      = blockIdx.z ? g_gt : g_xt;
    const float* xp = src + ((size_t)b*CC)*PIX + (size_t)h*WW;
    for (int i = threadIdx.x; i < 2048; i += 256) {
        int c = i >> 5, x4 = (i & 31) * 4;
        float4 v = *(const float4*)(xp + (size_t)c*PIX + x4);
        s[c*129 + x4+0]=v.x; s[c*129 + x4+1]=v.y; s[c*129 + x4+2]=v.z; s[c*129 + x4+3]=v.w;
    }
    __syncthreads();
    __half* op = dst + ((size_t)(b*HH + h)*WW)*CC;
    for (int i = threadIdx.x; i < 2048; i += 256) {
        int xx = i >> 4, c4 = (i & 15) * 4;
        uint2 o;
        o.x = pk16(s[(c4+0)*129 + xx], s[(c4+1)*129 + xx]);
        o.y = pk16(s[(c4+2)*129 + xx], s[(c4+3)*129 + xx]);
        *(uint2*)(op + (size_t)xx*CC + c4) = o;
    }
}

// ---------------------------------------------------------------------------
// Kernel 1: weight prep — fp32 -> fp16 hi/lo, packed in mma fragment order.
// ---------------------------------------------------------------------------
__global__ void k_prepw(const float* __restrict__ w_off, const float* __restrict__ w_mod,
                        const float* __restrict__ w_reg){
    int i = blockIdx.x*256 + threadIdx.x;
    if (i >= 18432) return;
    int q = i & 3, L = (i >> 2) & 31;
    { // offmod
        int nhalf = (i >> 7) & 1, ks = (i >> 8) & 3, chunk = i >> 10;
        int kk = chunk >> 1, half = chunk & 1;
        int oc = nhalf*16 + ((q >> 1) & 1)*8 + (L >> 2);
        int ch = ks*16 + (q & 1)*8 + (L & 3)*2;
        int c0 = half*64 + ch;
        float w0 = 0.f, w1 = 0.f;
        if (oc < 18)      { w0 = w_off[(oc*128 + c0)*9 + kk];       w1 = w_off[(oc*128 + c0 + 1)*9 + kk]; }
        else if (oc < 27) { w0 = w_mod[((oc-18)*128 + c0)*9 + kk];  w1 = w_mod[((oc-18)*128 + c0 + 1)*9 + kk]; }
        float h0 = __half2float(__float2half_rn(w0));
        float h1 = __half2float(__float2half_rn(w1));
        ((uint32_t*)g_oBh)[i] = pk16(h0, h1);
        ((uint32_t*)g_oBl)[i] = pk16(w0 - h0, w1 - h1);
    }
    { // deform
        int p = (i >> 7) & 1, nhalf = (i >> 8) & 1, ks = (i >> 9) & 3, kk = i >> 11;
        int oc = nhalf*32 + p*16 + ((q >> 1) & 1)*8 + (L >> 2);
        int ch = ks*16 + (q & 1)*8 + (L & 3)*2;
        float w0 = w_reg[(oc*64 + ch)*9 + kk], w1 = w_reg[(oc*64 + ch + 1)*9 + kk];
        float h0 = __half2float(__float2half_rn(w0));
        float h1 = __half2float(__float2half_rn(w1));
        ((uint32_t*)g_dBh)[i] = pk16(h0, h1);
        ((uint32_t*)g_dBl)[i] = pk16(w0 - h0, w1 - h1);
    }
}

// ---------------------------------------------------------------------------
// Kernel 2: offset+modulator conv (M=128, N=32(27), K=1152), HALO-STAGED.
// fp16 sources -> staging is pure uint4 copy. 4 CTAs/SM. (R16, proven)
// ---------------------------------------------------------------------------
#define OM_TILE 16640
#define OM_SMEM (33280 + 128)

__global__ __launch_bounds__(256,4) void k_offmod(const float* __restrict__ b_off,
                                                  const float* __restrict__ b_mod)
{
    extern __shared__ char smem_raw[];
    uint32_t sbr = smem_u32(smem_raw);
    uint32_t sb  = (sbr + 127) & ~127u;

    int t = threadIdx.x, wid = t >> 5, lid = t & 31;
    int mwid = wid & 3, nhalf = wid >> 2;
    int h = blockIdx.x, b = blockIdx.y;

    uint32_t aRowSel = (lid & 7) + ((lid >> 3) & 1) * 8;
    uint32_t aColSel = ((lid >> 4) & 1) * 16;

    float acc[16];
#pragma unroll
    for (int i = 0; i < 16; i++) acc[i] = 0.f;

    const uint4* xb = (const uint4*)g_xt;
    const uint4* gb = (const uint4*)g_gt;

    for (int dy = 0; dy < 3; dy++) {
        if (dy) __syncthreads();
        { // stage x & guide tiles: 130 rows (px = r-1) x 64 ch fp16 (8 uint4/row)
            int hy = h + dy - 1;
            bool rowok = (hy >= 0) && (hy < HH);
            size_t rowoff = ((size_t)b*HH + (rowok ? hy : 0))*WW;
            for (int j = t; j < 2080; j += 256) {
                int src = (j >= 1040);
                int jj = src ? j - 1040 : j;
                int r = jj >> 3, c8 = jj & 7;
                int px = r - 1;
                uint4 v = make_uint4(0,0,0,0);
                if (rowok && px >= 0 && px < WW) {
                    const uint4* bp = src ? gb : xb;
                    v = bp[(rowoff + px)*8 + c8];
                }
                uint32_t off = src*OM_TILE + r*128 + ((c8 ^ (r & 7)) * 16);
                sts4(sb + off, v.x, v.y, v.z, v.w);
            }
        }
        __syncthreads();

#pragma unroll
        for (int half = 0; half < 2; half++) {
            uint32_t tileB = sb + half*OM_TILE;
#pragma unroll
            for (int dx = 0; dx < 3; dx++) {
                int chunk = (dy*3 + dx)*2 + half;
                uint32_t swzdx = (((lid & 7) + dx) & 7) * 16;
#pragma unroll
                for (int ks = 0; ks < 4; ks++) {
                    uint4 BH = g_oBh[(chunk*8 + ks*2 + nhalf)*32 + lid];
                    uint4 BL = g_oBl[(chunk*8 + ks*2 + nhalf)*32 + lid];
                    uint32_t ah[8];
#pragma unroll
                    for (int m = 0; m < 2; m++) {
                        uint32_t R = mwid*32 + m*16 + aRowSel + dx;   // tile row = px + dx
                        uint32_t aa = tileB + R*128 + ((ks*32 + aColSel) ^ swzdx);
                        ldsm4(ah[m*4+0], ah[m*4+1], ah[m*4+2], ah[m*4+3], aa);
                    }
#pragma unroll
                    for (int m = 0; m < 2; m++) {
                        float* d0 = acc + (m*2+0)*4;
                        float* d1 = acc + (m*2+1)*4;
                        mma16816(d0, ah[m*4+0],ah[m*4+1],ah[m*4+2],ah[m*4+3], BH.x, BH.y);
                        mma16816(d0, ah[m*4+0],ah[m*4+1],ah[m*4+2],ah[m*4+3], BL.x, BL.y);
                        mma16816(d1, ah[m*4+0],ah[m*4+1],ah[m*4+2],ah[m*4+3], BH.z, BH.w);
                        mma16816(d1, ah[m*4+0],ah[m*4+1],ah[m*4+2],ah[m*4+3], BL.z, BL.w);
                    }
                }
            }
        }
    }

    // epilogue
    int g = lid >> 2, tig = lid & 3;
    int pixbase = h*WW;
#pragma unroll
    for (int m = 0; m < 2; m++)
#pragma unroll
    for (int n = 0; n < 2; n++)
#pragma unroll
    for (int r = 0; r < 4; r++) {
        int px = mwid*32 + m*16 + g + (r>>1)*8;
        int oc = nhalf*16 + n*8 + 2*tig + (r&1);
        float v = acc[(m*2+n)*4 + r];
        int pix = pixbase + px;
        if (oc < 18) {
            g_offset[(size_t)(b*18 + oc)*PIX + pix] = v + b_off[oc];
        } else if (oc < 27) {
            float z = v + b_mod[oc-18];
            g_mask[(size_t)(b*9 + oc-18)*PIX + pix] = 2.f / (1.f + expf(-z));
        }
    }
}

// ---------------------------------------------------------------------------
// Kernel 3: deformable conv (M=128, N=64, K=576), pipelined fp16 2-term.
// Gather: uint4 corner loads + packed HFMA2 bilinear (no cvt, no float math).
// 4 CTAs/SM single wave. B consumed in two halves.
// ---------------------------------------------------------------------------
#define DF_PB  0
#define DF_A0  8192
#define DF_A1  24576
#define DF_SMEM (40960 + 128)

__global__ __launch_bounds__(256,4) void k_deform(float* __restrict__ out)
{
    extern __shared__ char smem_raw[];
    uint32_t sbr = smem_u32(smem_raw);
    uint32_t sb  = (sbr + 127) & ~127u;
    char* sm0 = smem_raw + (sb - sbr);
    int* spi = (int*)(sm0 + DF_PB);
    uint32_t* spu = (uint32_t*)(sm0 + DF_PB);

    int t = threadIdx.x, wid = t >> 5, lid = t & 31;
    int mwid = wid & 3, nhalf = wid >> 2;
    int h = blockIdx.x, b = blockIdx.y;

    uint32_t aRowSel = (lid & 7) + ((lid >> 3) & 1) * 8;
    uint32_t aColSel = ((lid >> 4) & 1) * 16;
    uint32_t swz = (lid & 7) * 16;

    const uint4* xb = (const uint4*)(g_xt + (size_t)b*PIX*CC);

    float acc[32];
#pragma unroll
    for (int i = 0; i < 32; i++) acc[i] = 0.f;

#define DF_PARAMS(kk_, psel_) do {                                               \
    if (t < 128) {                                                               \
        int px_ = t;                                                              \
        int pix_ = h*WW + px_;                                                    \
        float oy_ = g_offset[((size_t)(b*18 + 2*(kk_)  ))*PIX + pix_];            \
        float ox_ = g_offset[((size_t)(b*18 + 2*(kk_)+1))*PIX + pix_];            \
        float m_  = g_mask  [((size_t)(b*9  + (kk_)    ))*PIX + pix_];            \
        int ky_ = (kk_)/3, kx_ = (kk_) - ky_*3;                                   \
        float py_  = oy_ + (float)(ky_ + h - 1);                                  \
        float pxf_ = ox_ + (float)(kx_ + px_ - 1);                                \
        float y0f_ = floorf(py_), x0f_ = floorf(pxf_);                            \
        int y0_ = (int)y0f_, x0_ = (int)x0f_;                                     \
        int y1_ = y0_ + 1,   x1_ = x0_ + 1;                                       \
        float wy1_ = py_ - y0f_,  wx1_ = pxf_ - x0f_;                             \
        float wy0_ = 1.f - wy1_, wx0_ = 1.f - wx1_;                               \
        bool vy0_ = (y0_>=0 && y0_<HH), vy1_ = (y1_>=0 && y1_<HH);                \
        bool vx0_ = (x0_>=0 && x0_<WW), vx1_ = (x1_>=0 && x1_<WW);                \
        int y0c_ = min(max(y0_,0),HH-1), y1c_ = min(max(y1_,0),HH-1);             \
        int x0c_ = min(max(x0_,0),WW-1), x1c_ = min(max(x1_,0),WW-1);             \
        int base_ = (psel_)*1024 + px_*8;                                         \
        spi[base_+0] = (y0c_*WW + x0c_)*8;                                        \
        spi[base_+1] = (y0c_*WW + x1c_)*8;                                        \
        spi[base_+2] = (y1c_*WW + x0c_)*8;                                        \
        spi[base_+3] = (y1c_*WW + x1c_)*8;                                        \
        float q00 = (vy0_&&vx0_) ? wy0_*wx0_*m_ : 0.f;                            \
        float q01 = (vy0_&&vx1_) ? wy0_*wx1_*m_ : 0.f;                            \
        float q10 = (vy1_&&vx0_) ? wy1_*wx0_*m_ : 0.f;                            \
        float q11 = (vy1_&&vx1_) ? wy1_*wx1_*m_ : 0.f;                            \
        spu[base_+4] = pk16(q00, q00);                                            \
        spu[base_+5] = pk16(q01, q01);                                            \
        spu[base_+6] = pk16(q10, q10);                                            \
        spu[base_+7] = pk16(q11, q11);                                            \
    } } while(0)

// gather: 128px x 8 lanes (8 ch each as uint4) = 1024 tasks, 4 iters; HFMA2 math
#define DF_GATHER(psel_, dH_) do {                                               \
    _Pragma("unroll")                                                            \
    for (int it_ = 0; it_ < 4; it_++) {                                          \
        int j_ = it_*256 + t;                                                    \
        int px_ = j_ >> 3, l8_ = j_ & 7;                                         \
        int base_ = (psel_)*1024 + px_*8;                                        \
        int i00 = spi[base_+0], i01 = spi[base_+1], i10 = spi[base_+2], i11 = spi[base_+3]; \
        uint32_t G00 = spu[base_+4], G01 = spu[base_+5], G10 = spu[base_+6], G11 = spu[base_+7]; \
        uint4 A_ = xb[i00 + l8_];                                                 \
        uint4 C_ = xb[i01 + l8_];                                                 \
        uint4 D_ = xb[i10 + l8_];                                                 \
        uint4 E_ = xb[i11 + l8_];                                                 \
        uint32_t r0 = bilin2(A_.x, C_.x, D_.x, E_.x, G00, G01, G10, G11);         \
        uint32_t r1 = bilin2(A_.y, C_.y, D_.y, E_.y, G00, G01, G10, G11);         \
        uint32_t r2 = bilin2(A_.z, C_.z, D_.z, E_.z, G00, G01, G10, G11);         \
        uint32_t r3 = bilin2(A_.w, C_.w, D_.w, E_.w, G00, G01, G10, G11);         \
        uint32_t off_ = px_*128 + ((l8_*16) ^ ((px_ & 7)*16));                    \
        sts4(sb + (dH_) + off_, r0, r1, r2, r3);                                  \
    } } while(0)

    // prologue
    DF_PARAMS(0, 0);
    __syncthreads();
    DF_GATHER(0, DF_A0);
    DF_PARAMS(1, 1);
    __syncthreads();

    for (int kk = 0; kk < 9; kk++) {
        int cs = kk & 1, ns = cs ^ 1;
        if (kk < 8) {
            if (ns) DF_GATHER(1, DF_A1);
            else    DF_GATHER(0, DF_A0);
        }
        if (kk < 7) DF_PARAMS(kk+2, cs);

        uint32_t aH = sb + (cs ? DF_A1 : DF_A0);
#pragma unroll
        for (int ks = 0; ks < 4; ks++) {
            int bi = (kk*16 + ks*4 + nhalf*2)*32 + lid;
            uint32_t ah[8];
#pragma unroll
            for (int m = 0; m < 2; m++) {
                uint32_t R = mwid*32 + m*16 + aRowSel;
                uint32_t aa = aH + R*128 + ((ks*32 + aColSel) ^ swz);
                ldsm4(ah[m*4+0], ah[m*4+1], ah[m*4+2], ah[m*4+3], aa);
            }
            { // first N-16 half
                uint4 BH = g_dBh[bi], BL = g_dBl[bi];
#pragma unroll
                for (int m = 0; m < 2; m++) {
                    float* d0 = acc + (m*4+0)*4;
                    float* d1 = acc + (m*4+1)*4;
                    mma16816(d0, ah[m*4+0],ah[m*4+1],ah[m*4+2],ah[m*4+3], BH.x, BH.y);
                    mma16816(d0, ah[m*4+0],ah[m*4+1],ah[m*4+2],ah[m*4+3], BL.x, BL.y);
                    mma16816(d1, ah[m*4+0],ah[m*4+1],ah[m*4+2],ah[m*4+3], BH.z, BH.w);
                    mma16816(d1, ah[m*4+0],ah[m*4+1],ah[m*4+2],ah[m*4+3], BL.z, BL.w);
                }
            }
            { // second N-16 half
                uint4 BH = g_dBh[bi + 32], BL = g_dBl[bi + 32];
#pragma unroll
                for (int m = 0; m < 2; m++) {
                    float* d2 = acc + (m*4+2)*4;
                    float* d3 = acc + (m*4+3)*4;
                    mma16816(d2, ah[m*4+0],ah[m*4+1],ah[m*4+2],ah[m*4+3], BH.x, BH.y);
                    mma16816(d2, ah[m*4+0],ah[m*4+1],ah[m*4+2],ah[m*4+3], BL.x, BL.y);
                    mma16816(d3, ah[m*4+0],ah[m*4+1],ah[m*4+2],ah[m*4+3], BH.z, BH.w);
                    mma16816(d3, ah[m*4+0],ah[m*4+1],ah[m*4+2],ah[m*4+3], BL.z, BL.w);
                }
            }
        }
        __syncthreads();
    }

    // epilogue
    int g = lid >> 2, tig = lid & 3;
    size_t ob = (size_t)b*64*PIX + (size_t)h*WW;
#pragma unroll
    for (int n = 0; n < 4; n++)
#pragma unroll
    for (int m = 0; m < 2; m++)
#pragma unroll
    for (int r = 0; r < 4; r++) {
        int px = mwid*32 + m*16 + g + (r>>1)*8;
        int oc = nhalf*32 + n*8 + 2*tig + (r&1);
        out[ob + (size_t)oc*PIX + px] = acc[(m*4+n)*4 + r];
    }
}

// ---------------------------------------------------------------------------
extern "C" void kernel_launch(void* const* d_in, const int* in_sizes, int n_in,
                              void* d_out, int out_size)
{
    const float* x     = (const float*)d_in[0];
    const float* guide = (const float*)d_in[1];
    const float* w_off = (const float*)d_in[2];
    const float* b_off = (const float*)d_in[3];
    const float* w_mod = (const float*)d_in[4];
    const float* b_mod = (const float*)d_in[5];
    const float* w_reg = (const float*)d_in[6];
    float* out = (float*)d_out;

    cudaFuncSetAttribute(k_offmod, cudaFuncAttributeMaxDynamicSharedMemorySize, OM_SMEM);
    cudaFuncSetAttribute(k_deform, cudaFuncAttributeMaxDynamicSharedMemorySize, DF_SMEM);

    k_transpose<<<dim3(HH, BB, 2), 256>>>(x, guide);
    k_prepw    <<<72, 256>>>(w_off, w_mod, w_reg);
    k_offmod   <<<dim3(HH, BB), 256, OM_SMEM>>>(b_off, b_mod);
    k_deform   <<<dim3(HH, BB), 256, DF_SMEM>>>(out);
}